// round 2
// baseline (speedup 1.0000x reference)
#include <cuda_runtime.h>
#include <cstdint>

#define Bb 8
#define Cc 256
#define Nn 4096
#define Dd 16
#define BM 64
#define BN 32

// ---------------- scratch (static device arrays; no allocs) ----------------
__device__ float g_Q [(size_t)Bb * Nn * Dd];          // [B,N,D]
__device__ float g_K [(size_t)Bb * Dd * Nn];          // [B,D,N]
__device__ float g_VT[(size_t)Bb * Nn * Cc];          // [B,N,C]  (V transposed)
__device__ float g_OA[(size_t)Bb * Cc * Nn];          // [B,C,N]  attention output

// ---------------- packed f32x2 helpers ----------------
static __device__ __forceinline__ unsigned long long pack2(float x, float y) {
    unsigned long long r;
    asm("mov.b64 %0, {%1,%2};" : "=l"(r) : "f"(x), "f"(y));
    return r;
}
static __device__ __forceinline__ void unpack2(unsigned long long v, float &x, float &y) {
    asm("mov.b64 {%0,%1}, %2;" : "=f"(x), "=f"(y) : "l"(v));
}
static __device__ __forceinline__ void ffma2(unsigned long long &acc,
                                             unsigned long long a,
                                             unsigned long long b) {
    asm("fma.rn.f32x2 %0, %1, %2, %0;" : "+l"(acc) : "l"(a), "l"(b));
}
static __device__ __forceinline__ void fmul2(unsigned long long &a, unsigned long long b) {
    asm("mul.rn.f32x2 %0, %0, %1;" : "+l"(a) : "l"(b));
}

// ---------------- q/k projection: q=[B,N,D], k=[B,D,N] ----------------
__global__ __launch_bounds__(128) void qkproj_kernel(
    const float* __restrict__ x,
    const float* __restrict__ Wq, const float* __restrict__ bq,
    const float* __restrict__ Wk, const float* __restrict__ bk)
{
    __shared__ float wq[Dd * Cc];
    __shared__ float wk[Dd * Cc];
    int t = threadIdx.x;
    for (int i = t; i < Dd * Cc; i += 128) { wq[i] = Wq[i]; wk[i] = Wk[i]; }
    __syncthreads();

    int b = blockIdx.y;
    int n = blockIdx.x * 128 + t;

    float qa[Dd], ka[Dd];
#pragma unroll
    for (int d = 0; d < Dd; d++) { qa[d] = 0.f; ka[d] = 0.f; }

    const float* xp = x + (size_t)b * Cc * Nn + n;
#pragma unroll 4
    for (int c = 0; c < Cc; c++) {
        float xv = xp[(size_t)c * Nn];
#pragma unroll
        for (int d = 0; d < Dd; d++) {
            qa[d] += wq[d * Cc + c] * xv;
            ka[d] += wk[d * Cc + c] * xv;
        }
    }
    float* qo = g_Q + ((size_t)b * Nn + n) * Dd;
#pragma unroll
    for (int d = 0; d < Dd; d++) qo[d] = qa[d] + bq[d];
#pragma unroll
    for (int d = 0; d < Dd; d++) g_K[((size_t)b * Dd + d) * Nn + n] = ka[d] + bk[d];
}

// ---------------- V projection: VT[B,N,C] = (Wv @ x + bv)^T ----------------
__global__ __launch_bounds__(256) void vproj_kernel(
    const float* __restrict__ x,
    const float* __restrict__ Wv, const float* __restrict__ bv)
{
    __shared__ float Wt[64 * 65];
    __shared__ float Xt[64 * 65];
    int t  = threadIdx.x;
    int tr = t >> 4, tc = t & 15;
    int n0 = blockIdx.x * 64;
    int m0 = blockIdx.y * 64;
    int b  = blockIdx.z;

    float acc[4][4];
#pragma unroll
    for (int r = 0; r < 4; r++)
#pragma unroll
        for (int i = 0; i < 4; i++) acc[r][i] = 0.f;

    for (int kc = 0; kc < 4; kc++) {
        int k0 = kc * 64;
        __syncthreads();
#pragma unroll
        for (int l = 0; l < 16; l++) {
            int flat = t + l * 256;
            int rr = flat >> 6, kk = flat & 63;
            Wt[rr * 65 + kk] = Wv[(m0 + rr) * Cc + k0 + kk];
            Xt[rr * 65 + kk] = x[((size_t)(b * Cc + k0 + rr)) * Nn + n0 + kk];
        }
        __syncthreads();
#pragma unroll 8
        for (int kk = 0; kk < 64; kk++) {
            float av[4], bx[4];
#pragma unroll
            for (int r = 0; r < 4; r++) av[r] = Wt[(tr * 4 + r) * 65 + kk];
#pragma unroll
            for (int i = 0; i < 4; i++) bx[i] = Xt[kk * 65 + tc + 16 * i];
#pragma unroll
            for (int r = 0; r < 4; r++)
#pragma unroll
                for (int i = 0; i < 4; i++) acc[r][i] += av[r] * bx[i];
        }
    }
    float bias[4];
#pragma unroll
    for (int r = 0; r < 4; r++) bias[r] = bv[m0 + tr * 4 + r];

    // transpose through smem -> coalesced VT store
    __syncthreads();
#pragma unroll
    for (int r = 0; r < 4; r++)
#pragma unroll
        for (int i = 0; i < 4; i++)
            Wt[(tc + 16 * i) * 65 + tr * 4 + r] = acc[r][i] + bias[r];
    __syncthreads();
#pragma unroll
    for (int l = 0; l < 16; l++) {
        int flat = t + l * 256;
        int nl = flat >> 6, ml = flat & 63;
        g_VT[((size_t)(b * Nn + n0 + nl)) * Cc + m0 + ml] = Wt[nl * 65 + ml];
    }
}

// ---------------- fused flash attention: OA[B,C,N] ----------------
// smem carve (floats)
#define QS_OFF    0        // 64*17 = 1088
#define KS_OFF    1088     // 16*33 = 528
#define SS_OFF    1616     // 64*33 = 2112
#define VS_OFF    3728     // 32*258 = 8256  (8B aligned: 3728*4 = 14912)
#define RMAX_OFF  11984
#define RSUM_OFF  12048
#define RCORR_OFF 12112
#define SMEM_FLOATS 12176  // 48,704 B < 48 KB

__global__ __launch_bounds__(256, 2) void attn_kernel()
{
    __shared__ __align__(16) float S[SMEM_FLOATS];
    int t  = threadIdx.x;
    int tr = t >> 4, tc = t & 15;
    int b  = blockIdx.y;
    int m0 = blockIdx.x * BM;

    // load q tile [64,16]
#pragma unroll
    for (int l = 0; l < 4; l++) {
        int flat = t + l * 256;
        int m = flat >> 4, d = flat & 15;
        S[QS_OFF + m * 17 + d] = g_Q[((size_t)(b * Nn + m0 + m)) * Dd + d];
    }
    if (t < BM) { S[RMAX_OFF + t] = -1e30f; S[RSUM_OFF + t] = 0.f; }

    // o accumulators: 4 m-rows x 16 e (8 packed pairs), e = 2*tc + 32*i (+0/+1)
    unsigned long long o2[32];
#pragma unroll
    for (int i = 0; i < 32; i++) o2[i] = 0ull;

    const unsigned long long* vsd = reinterpret_cast<const unsigned long long*>(S + VS_OFF);
    float2* vs2 = reinterpret_cast<float2*>(S + VS_OFF);
    const float2* VT2 = reinterpret_cast<const float2*>(g_VT);

    for (int it = 0; it < Nn / BN; it++) {
        int n0 = it * BN;
        __syncthreads();
        // k tile [16,32]
#pragma unroll
        for (int l = 0; l < 2; l++) {
            int flat = t + l * 256;
            int d = flat >> 5, j = flat & 31;
            S[KS_OFF + d * 33 + j] = g_K[((size_t)(b * Dd + d)) * Nn + n0 + j];
        }
        // v tile [32,256] as float2, row stride 129 float2 (=258 floats)
#pragma unroll
        for (int l = 0; l < 16; l++) {
            int flat = t + l * 256;
            int j = flat >> 7, e2 = flat & 127;
            vs2[j * 129 + e2] = VT2[((size_t)(b * Nn + n0 + j)) * 128 + e2];
        }
        __syncthreads();

        // QK: s[m][j], m = tr*4+r, j = tc + 16*jj
        float sa[4][2];
#pragma unroll
        for (int r = 0; r < 4; r++) { sa[r][0] = 0.f; sa[r][1] = 0.f; }
#pragma unroll
        for (int d = 0; d < Dd; d++) {
            float k0v = S[KS_OFF + d * 33 + tc];
            float k1v = S[KS_OFF + d * 33 + tc + 16];
#pragma unroll
            for (int r = 0; r < 4; r++) {
                float qv = S[QS_OFF + (tr * 4 + r) * 17 + d];
                sa[r][0] += qv * k0v;
                sa[r][1] += qv * k1v;
            }
        }
#pragma unroll
        for (int r = 0; r < 4; r++)
#pragma unroll
            for (int jj = 0; jj < 2; jj++) {
                float s = 0.25f * sa[r][jj];               // scale = D^-0.5
                s = fminf(fmaxf(s, -50.f), 50.f);          // clip BEFORE softmax
                S[SS_OFF + (tr * 4 + r) * 33 + tc + 16 * jj] = s;
            }
        __syncthreads();

        // online softmax, one thread per row
        if (t < BM) {
            float om = S[RMAX_OFF + t];
            float tm = -1e30f;
#pragma unroll 8
            for (int j = 0; j < BN; j++) tm = fmaxf(tm, S[SS_OFF + t * 33 + j]);
            float nm = fmaxf(om, tm);
            float corr = __expf(om - nm);                  // first iter: exp(-inf)=0
            float sum = 0.f;
#pragma unroll 8
            for (int j = 0; j < BN; j++) {
                float p = __expf(S[SS_OFF + t * 33 + j] - nm);
                S[SS_OFF + t * 33 + j] = p;
                sum += p;
            }
            S[RSUM_OFF + t]  = S[RSUM_OFF + t] * corr + sum;
            S[RMAX_OFF + t]  = nm;
            S[RCORR_OFF + t] = corr;
        }
        __syncthreads();

        // rescale accumulators by corr
#pragma unroll
        for (int r = 0; r < 4; r++) {
            float c = S[RCORR_OFF + tr * 4 + r];
            unsigned long long c2 = pack2(c, c);
#pragma unroll
            for (int i = 0; i < 8; i++) fmul2(o2[r * 8 + i], c2);
        }
        // PV: o[m][e-pair] += p[m][j] * v[j][e-pair]   (packed FFMA2)
        for (int j = 0; j < BN; j++) {
            unsigned long long vv[8];
#pragma unroll
            for (int i = 0; i < 8; i++) vv[i] = vsd[j * 129 + tc + 16 * i];
            unsigned long long pv[4];
#pragma unroll
            for (int r = 0; r < 4; r++) {
                float p = S[SS_OFF + (tr * 4 + r) * 33 + j];
                pv[r] = pack2(p, p);
            }
#pragma unroll
            for (int r = 0; r < 4; r++)
#pragma unroll
                for (int i = 0; i < 8; i++)
                    ffma2(o2[r * 8 + i], pv[r], vv[i]);
        }
    }
    __syncthreads();

    float inv[4];
#pragma unroll
    for (int r = 0; r < 4; r++) inv[r] = 1.0f / S[RSUM_OFF + tr * 4 + r];

    // write OA[b][e][m0+..] transposed via smem staging, two e-halves of 128
    for (int h = 0; h < 2; h++) {
        __syncthreads();
#pragma unroll
        for (int r = 0; r < 4; r++)
#pragma unroll
            for (int i2 = 0; i2 < 4; i2++) {
                float lo, hi;
                unpack2(o2[r * 8 + h * 4 + i2], lo, hi);
                int le = 2 * tc + 32 * i2;
                S[le * 65 + tr * 4 + r]       = lo * inv[r];
                S[(le + 1) * 65 + tr * 4 + r] = hi * inv[r];
            }
        __syncthreads();
#pragma unroll
        for (int l = 0; l < 32; l++) {
            int flat = t + l * 256;
            int le = flat >> 6, ml = flat & 63;
            g_OA[((size_t)(b * Cc + h * 128 + le)) * Nn + m0 + ml] = S[le * 65 + ml];
        }
    }
}

// ---------------- output projection + residual: out = g*(Wo@OA + bo) + x ----------------
__global__ __launch_bounds__(256) void outproj_kernel(
    const float* __restrict__ x,
    const float* __restrict__ Wo, const float* __restrict__ bo,
    const float* __restrict__ gamma, float* __restrict__ out)
{
    __shared__ float Wt[64 * 65];
    __shared__ float Xt[64 * 65];
    int t  = threadIdx.x;
    int tr = t >> 4, tc = t & 15;
    int n0 = blockIdx.x * 64;
    int m0 = blockIdx.y * 64;
    int b  = blockIdx.z;

    float acc[4][4];
#pragma unroll
    for (int r = 0; r < 4; r++)
#pragma unroll
        for (int i = 0; i < 4; i++) acc[r][i] = 0.f;

    for (int kc = 0; kc < 4; kc++) {
        int k0 = kc * 64;
        __syncthreads();
#pragma unroll
        for (int l = 0; l < 16; l++) {
            int flat = t + l * 256;
            int rr = flat >> 6, kk = flat & 63;
            Wt[rr * 65 + kk] = Wo[(m0 + rr) * Cc + k0 + kk];
            Xt[rr * 65 + kk] = g_OA[((size_t)(b * Cc + k0 + rr)) * Nn + n0 + kk];
        }
        __syncthreads();
#pragma unroll 8
        for (int kk = 0; kk < 64; kk++) {
            float av[4], bx[4];
#pragma unroll
            for (int r = 0; r < 4; r++) av[r] = Wt[(tr * 4 + r) * 65 + kk];
#pragma unroll
            for (int i = 0; i < 4; i++) bx[i] = Xt[kk * 65 + tc + 16 * i];
#pragma unroll
            for (int r = 0; r < 4; r++)
#pragma unroll
                for (int i = 0; i < 4; i++) acc[r][i] += av[r] * bx[i];
        }
    }
    float g = fminf(fmaxf(gamma[0], 0.f), 1.f);
#pragma unroll
    for (int r = 0; r < 4; r++) {
        int m = m0 + tr * 4 + r;
        float bb = bo[m];
#pragma unroll
        for (int i = 0; i < 4; i++) {
            int n = n0 + tc + 16 * i;
            size_t idx = ((size_t)(b * Cc + m)) * Nn + n;
            out[idx] = g * (acc[r][i] + bb) + x[idx];
        }
    }
}

// ---------------- launcher ----------------
extern "C" void kernel_launch(void* const* d_in, const int* in_sizes, int n_in,
                              void* d_out, int out_size)
{
    const float* x     = (const float*)d_in[0];
    const float* Wq    = (const float*)d_in[1];
    const float* bq    = (const float*)d_in[2];
    const float* Wk    = (const float*)d_in[3];
    const float* bk    = (const float*)d_in[4];
    const float* Wv    = (const float*)d_in[5];
    const float* bv    = (const float*)d_in[6];
    const float* Wo    = (const float*)d_in[7];
    const float* bo    = (const float*)d_in[8];
    const float* gamma = (const float*)d_in[9];
    float* out = (float*)d_out;

    qkproj_kernel<<<dim3(Nn / 128, Bb), 128>>>(x, Wq, bq, Wk, bk);
    vproj_kernel <<<dim3(Nn / 64, Cc / 64, Bb), 256>>>(x, Wv, bv);
    attn_kernel  <<<dim3(Nn / BM, Bb), 256>>>();
    outproj_kernel<<<dim3(Nn / 64, Cc / 64, Bb), 256>>>(x, Wo, bo, gamma, out);
}

// round 4
// speedup vs baseline: 1.6327x; 1.6327x over previous
#include <cuda_runtime.h>
#include <cuda_bf16.h>
#include <cstdint>

#define Bb 8
#define Cc 256
#define Nn 4096
#define Dd 16
#define BM 64
#define BN 64
#define NTILES (Nn / BN)

typedef unsigned long long ull;

// ---------------- scratch ----------------
__device__ float g_Q[(size_t)Bb * Nn * Dd];            // [B,N,D]
__device__ float g_K[(size_t)Bb * Dd * Nn];            // [B,D,N]
__device__ __nv_bfloat16 g_VT[(size_t)Bb * Nn * Cc];   // [B,N,C] bf16 (V transposed)
__device__ float g_OA[(size_t)Bb * Cc * Nn];           // [B,C,N]

// ---------------- f32x2 helpers ----------------
static __device__ __forceinline__ ull pack2(float x, float y) {
    ull r; asm("mov.b64 %0, {%1,%2};" : "=l"(r) : "f"(x), "f"(y)); return r;
}
static __device__ __forceinline__ void unpack2(ull v, float &x, float &y) {
    asm("mov.b64 {%0,%1}, %2;" : "=f"(x), "=f"(y) : "l"(v));
}
static __device__ __forceinline__ void ffma2(ull &acc, ull a, ull b) {
    asm("fma.rn.f32x2 %0, %1, %2, %0;" : "+l"(acc) : "l"(a), "l"(b));
}

// ---------------- mma / ldmatrix helpers (base ISA, no 'a' features) ----------------
static __device__ __forceinline__ uint32_t smem_u32(const void* p) {
    uint32_t a;
    asm("{ .reg .u64 t; cvta.to.shared.u64 t, %1; cvt.u32.u64 %0, t; }" : "=r"(a) : "l"(p));
    return a;
}
static __device__ __forceinline__ void ldsm_x4(uint32_t &r0, uint32_t &r1, uint32_t &r2, uint32_t &r3, uint32_t addr) {
    asm volatile("ldmatrix.sync.aligned.m8n8.x4.shared.b16 {%0,%1,%2,%3}, [%4];"
                 : "=r"(r0), "=r"(r1), "=r"(r2), "=r"(r3) : "r"(addr));
}
static __device__ __forceinline__ void ldsm_x4t(uint32_t &r0, uint32_t &r1, uint32_t &r2, uint32_t &r3, uint32_t addr) {
    asm volatile("ldmatrix.sync.aligned.m8n8.x4.trans.shared.b16 {%0,%1,%2,%3}, [%4];"
                 : "=r"(r0), "=r"(r1), "=r"(r2), "=r"(r3) : "r"(addr));
}
static __device__ __forceinline__ void mma16816(float* d, const uint32_t* a, uint32_t b0, uint32_t b1) {
    asm volatile("mma.sync.aligned.m16n8k16.row.col.f32.bf16.bf16.f32 "
                 "{%0,%1,%2,%3}, {%4,%5,%6,%7}, {%8,%9}, {%0,%1,%2,%3};"
                 : "+f"(d[0]), "+f"(d[1]), "+f"(d[2]), "+f"(d[3])
                 : "r"(a[0]), "r"(a[1]), "r"(a[2]), "r"(a[3]), "r"(b0), "r"(b1));
}

// ---------------- q/k projection ----------------
__global__ __launch_bounds__(128) void qkproj_kernel(
    const float* __restrict__ x,
    const float* __restrict__ Wq, const float* __restrict__ bq,
    const float* __restrict__ Wk, const float* __restrict__ bk)
{
    __shared__ __align__(16) float wq[Cc * Dd];
    __shared__ __align__(16) float wk[Cc * Dd];
    int t = threadIdx.x;
    for (int i = t; i < Cc * Dd; i += 128) {
        int d = i >> 8, c = i & 255;
        wq[c * 16 + d] = Wq[i];
        wk[c * 16 + d] = Wk[i];
    }
    __syncthreads();
    int b = blockIdx.y;
    int n = blockIdx.x * 128 + t;

    ull qa[8], ka[8];
#pragma unroll
    for (int j = 0; j < 8; j++) { qa[j] = 0ull; ka[j] = 0ull; }
    const float* xp = x + (size_t)b * Cc * Nn + n;
#pragma unroll 4
    for (int c = 0; c < Cc; c++) {
        float xv = xp[(size_t)c * Nn];
        ull xx = pack2(xv, xv);
        const ulonglong2* wqp = (const ulonglong2*)(wq + c * 16);
        const ulonglong2* wkp = (const ulonglong2*)(wk + c * 16);
#pragma unroll
        for (int j = 0; j < 4; j++) {
            ulonglong2 a = wqp[j];
            ffma2(qa[2 * j], xx, a.x);
            ffma2(qa[2 * j + 1], xx, a.y);
            ulonglong2 kk2 = wkp[j];
            ffma2(ka[2 * j], xx, kk2.x);
            ffma2(ka[2 * j + 1], xx, kk2.y);
        }
    }
    float q[16], k[16];
#pragma unroll
    for (int j = 0; j < 8; j++) { unpack2(qa[j], q[2 * j], q[2 * j + 1]); unpack2(ka[j], k[2 * j], k[2 * j + 1]); }
    float* qo = g_Q + ((size_t)b * Nn + n) * Dd;
#pragma unroll
    for (int d = 0; d < 16; d++) qo[d] = q[d] + bq[d];
#pragma unroll
    for (int d = 0; d < 16; d++) g_K[((size_t)b * Dd + d) * Nn + n] = k[d] + bk[d];
}

// ---------------- GEMM smem layout (vproj/outproj): dyn smem ----------------
#define GP_WD 0
#define GP_XT 33280
#define GP_BYTES (33280 + 17408)

// ---------------- V projection -> bf16 g_VT[B,N,C] ----------------
__global__ __launch_bounds__(256) void vproj_kernel(
    const float* __restrict__ x,
    const float* __restrict__ Wv, const float* __restrict__ bv)
{
    extern __shared__ __align__(16) char gsm[];
    float2* Wd = (float2*)(gsm + GP_WD);
    float*  Xt = (float*)(gsm + GP_XT);
    int t = threadIdx.x, tr = t >> 4, tc = t & 15;
    int n0 = blockIdx.x * 64, m0 = blockIdx.y * 64, b = blockIdx.z;

    ull acc[4][2];
#pragma unroll
    for (int r = 0; r < 4; r++) { acc[r][0] = 0ull; acc[r][1] = 0ull; }

    for (int kc = 0; kc < 4; kc++) {
        int k0 = kc * 64;
        __syncthreads();
#pragma unroll
        for (int l = 0; l < 16; l++) {
            int flat = t + l * 256;
            int rr = flat >> 6, kk = flat & 63;
            float w = Wv[(m0 + rr) * Cc + k0 + kk];
            Wd[kk * 65 + rr] = make_float2(w, w);
            Xt[rr * 68 + kk] = x[((size_t)(b * Cc + k0 + rr)) * Nn + n0 + kk];
        }
        __syncthreads();
#pragma unroll 4
        for (int kk = 0; kk < 64; kk++) {
            ulonglong2 xv = *(const ulonglong2*)(Xt + kk * 68 + tc * 4);
            const ull* wp = (const ull*)(Wd + kk * 65 + tr * 4);
#pragma unroll
            for (int r = 0; r < 4; r++) {
                ull w2 = wp[r];
                ffma2(acc[r][0], w2, xv.x);
                ffma2(acc[r][1], w2, xv.y);
            }
        }
    }
    // unpack, add bias: f[r][i] = value(m = m0+tr*4+r, n = n0+tc*4+i)
    float f[4][4];
#pragma unroll
    for (int r = 0; r < 4; r++) {
        float bb = bv[m0 + tr * 4 + r];
        unpack2(acc[r][0], f[r][0], f[r][1]);
        unpack2(acc[r][1], f[r][2], f[r][3]);
#pragma unroll
        for (int i = 0; i < 4; i++) f[r][i] += bb;
    }
    // transpose to bf16 [n_local][m_local] then coalesced store
    __syncthreads();
    __nv_bfloat16* Tb = (__nv_bfloat16*)(gsm + GP_XT);
#pragma unroll
    for (int i = 0; i < 4; i++) {
        __nv_bfloat162 p0 = __floats2bfloat162_rn(f[0][i], f[1][i]);
        __nv_bfloat162 p1 = __floats2bfloat162_rn(f[2][i], f[3][i]);
        *(__nv_bfloat162*)(Tb + (tc * 4 + i) * 72 + tr * 4)     = p0;
        *(__nv_bfloat162*)(Tb + (tc * 4 + i) * 72 + tr * 4 + 2) = p1;
    }
    __syncthreads();
    {
        int n = t >> 2, c = t & 3;
        const uint4* src = (const uint4*)(Tb + n * 72 + c * 16);
        uint4* dst = (uint4*)(g_VT + ((size_t)(b * Nn + n0 + n)) * Cc + m0 + c * 16);
        dst[0] = src[0];
        dst[1] = src[1];
    }
}

// ---------------- fused attention: QK scalar + PV via mma.sync ----------------
__global__ __launch_bounds__(256, 2) void attn_kernel()
{
    __shared__ __align__(16) float Ks[16 * 68];                 // 4352 B
    __shared__ __align__(16) __nv_bfloat16 Ps[64 * 72];         // 9216 B (stride 144B)
    __shared__ __align__(16) __nv_bfloat16 Vs[64 * 264];        // 33792 B (stride 528B)
    __shared__ float rs_s[64];

    int t = threadIdx.x, b = blockIdx.y, m0 = blockIdx.x * BM;
    int wid = t >> 5, lane = t & 31;
    int mg = wid & 1, eg = wid >> 1;      // warp: rows mg*32..+32, cols eg*64..+64
    int mq = t >> 2, jq = (t & 3) * 16;   // QK: row mq, 16 j at jq

    uint32_t PsU = smem_u32(Ps);
    uint32_t VsU = smem_u32(Vs);

    // q regs (scale folded), duplicated packs for ffma2
    ull q2[16];
    {
        const float4* qp = (const float4*)(g_Q + ((size_t)(b * Nn + m0 + mq)) * Dd);
#pragma unroll
        for (int j = 0; j < 4; j++) {
            float4 a = qp[j];
            q2[4 * j]     = pack2(a.x * 0.25f, a.x * 0.25f);
            q2[4 * j + 1] = pack2(a.y * 0.25f, a.y * 0.25f);
            q2[4 * j + 2] = pack2(a.z * 0.25f, a.z * 0.25f);
            q2[4 * j + 3] = pack2(a.w * 0.25f, a.w * 0.25f);
        }
    }

    float acc[2][8][4];
#pragma unroll
    for (int i = 0; i < 2; i++)
#pragma unroll
        for (int j = 0; j < 8; j++)
#pragma unroll
            for (int k = 0; k < 4; k++) acc[i][j][k] = 0.f;

    const float* kb = g_K + (size_t)b * Dd * Nn;
    const __nv_bfloat16* vb = g_VT + (size_t)b * Nn * Cc;
    float rsum = 0.f;

    for (int it = 0; it < NTILES; it++) {
        int n0 = it * BN;
        __syncthreads();   // prior mma reads of Ps/Vs complete
        // K tile [16][64] fp32
        {
            int d = t >> 4, j4 = t & 15;
            *(float4*)(Ks + d * 68 + j4 * 4) = *(const float4*)(kb + (size_t)d * Nn + n0 + j4 * 4);
        }
        // V tile [64 j][256 e] bf16
        {
            int j = t >> 2, c = t & 3;
            const uint4* src = (const uint4*)(vb + ((size_t)(n0 + j)) * Cc + c * 64);
            uint4* dst = (uint4*)((char*)Vs + j * 528 + c * 128);
#pragma unroll
            for (int u = 0; u < 8; u++) dst[u] = src[u];
        }
        __syncthreads();

        // QK: 16 j for (mq, jq)
        ull acc2[8];
#pragma unroll
        for (int jp = 0; jp < 8; jp++) acc2[jp] = 0ull;
#pragma unroll
        for (int d = 0; d < 16; d++) {
            const ulonglong2* kp = (const ulonglong2*)(Ks + d * 68 + jq);
#pragma unroll
            for (int u = 0; u < 4; u++) {
                ulonglong2 kv = kp[u];
                ffma2(acc2[2 * u],     q2[d], kv.x);
                ffma2(acc2[2 * u + 1], q2[d], kv.y);
            }
        }
        uint32_t pb[8];
#pragma unroll
        for (int jp = 0; jp < 8; jp++) {
            float s0, s1;
            unpack2(acc2[jp], s0, s1);
            s0 = fminf(fmaxf(s0, -50.f), 50.f);
            s1 = fminf(fmaxf(s1, -50.f), 50.f);
            float p0 = __expf(s0), p1 = __expf(s1);
            rsum += p0 + p1;
            __nv_bfloat162 h2 = __floats2bfloat162_rn(p0, p1);
            pb[jp] = *(uint32_t*)&h2;
        }
        {
            uint4* pst = (uint4*)((char*)Ps + mq * 144 + jq * 2);
            pst[0] = make_uint4(pb[0], pb[1], pb[2], pb[3]);
            pst[1] = make_uint4(pb[4], pb[5], pb[6], pb[7]);
        }
        __syncthreads();

        // PV via mma.sync: warp covers m32 x e64
#pragma unroll
        for (int ks = 0; ks < 4; ks++) {
            uint32_t a0[4], a1[4];
            uint32_t arow = PsU + (mg * 32 + (lane & 15)) * 144 + ks * 32 + (lane >> 4) * 16;
            ldsm_x4(a0[0], a0[1], a0[2], a0[3], arow);
            ldsm_x4(a1[0], a1[1], a1[2], a1[3], arow + 16 * 144);
#pragma unroll
            for (int ep = 0; ep < 4; ep++) {
                uint32_t b0, b1, b2, b3;
                uint32_t baddr = VsU + (ks * 16 + (lane & 15)) * 528 +
                                 (eg * 64 + ep * 16 + (lane >> 4) * 8) * 2;
                ldsm_x4t(b0, b1, b2, b3, baddr);
                mma16816(acc[0][2 * ep],     a0, b0, b1);
                mma16816(acc[0][2 * ep + 1], a0, b2, b3);
                mma16816(acc[1][2 * ep],     a1, b0, b1);
                mma16816(acc[1][2 * ep + 1], a1, b2, b3);
            }
        }
    }
    // row sums (4 threads per row)
    rsum += __shfl_xor_sync(0xffffffffu, rsum, 1);
    rsum += __shfl_xor_sync(0xffffffffu, rsum, 2);
    if ((t & 3) == 0) rs_s[mq] = rsum;
    __syncthreads();

    // epilogue: normalize + store to g_OA[b, e, m0+m]
    float* ob = g_OA + (size_t)b * Cc * Nn + m0;
#pragma unroll
    for (int mt = 0; mt < 2; mt++) {
        int r0 = mg * 32 + mt * 16 + (lane >> 2);
        float inv0 = 1.0f / rs_s[r0];
        float inv1 = 1.0f / rs_s[r0 + 8];
#pragma unroll
        for (int nt = 0; nt < 8; nt++) {
            int e = eg * 64 + nt * 8 + (lane & 3) * 2;
            float* p = ob + (size_t)e * Nn;
            p[r0]          = acc[mt][nt][0] * inv0;
            p[Nn + r0]     = acc[mt][nt][1] * inv0;
            p[r0 + 8]      = acc[mt][nt][2] * inv1;
            p[Nn + r0 + 8] = acc[mt][nt][3] * inv1;
        }
    }
}

// ---------------- output projection + residual ----------------
__global__ __launch_bounds__(256) void outproj_kernel(
    const float* __restrict__ x,
    const float* __restrict__ Wo, const float* __restrict__ bo,
    const float* __restrict__ gamma, float* __restrict__ out)
{
    extern __shared__ __align__(16) char gsm[];
    float2* Wd = (float2*)(gsm + GP_WD);
    float*  Xt = (float*)(gsm + GP_XT);
    int t = threadIdx.x, tr = t >> 4, tc = t & 15;
    int n0 = blockIdx.x * 64, m0 = blockIdx.y * 64, b = blockIdx.z;

    ull acc[4][2];
#pragma unroll
    for (int r = 0; r < 4; r++) { acc[r][0] = 0ull; acc[r][1] = 0ull; }

    for (int kc = 0; kc < 4; kc++) {
        int k0 = kc * 64;
        __syncthreads();
#pragma unroll
        for (int l = 0; l < 16; l++) {
            int flat = t + l * 256;
            int rr = flat >> 6, kk = flat & 63;
            float w = Wo[(m0 + rr) * Cc + k0 + kk];
            Wd[kk * 65 + rr] = make_float2(w, w);
            Xt[rr * 68 + kk] = g_OA[((size_t)(b * Cc + k0 + rr)) * Nn + n0 + kk];
        }
        __syncthreads();
#pragma unroll 4
        for (int kk = 0; kk < 64; kk++) {
            ulonglong2 xv = *(const ulonglong2*)(Xt + kk * 68 + tc * 4);
            const ull* wp = (const ull*)(Wd + kk * 65 + tr * 4);
#pragma unroll
            for (int r = 0; r < 4; r++) {
                ull w2 = wp[r];
                ffma2(acc[r][0], w2, xv.x);
                ffma2(acc[r][1], w2, xv.y);
            }
        }
    }
    float g = fminf(fmaxf(gamma[0], 0.f), 1.f);
#pragma unroll
    for (int r = 0; r < 4; r++) {
        int m = m0 + tr * 4 + r;
        float bb = bo[m];
        size_t idx = ((size_t)(b * Cc + m)) * Nn + n0 + tc * 4;
        float4 xr = *(const float4*)(x + idx);
        float f0, f1, f2, f3;
        unpack2(acc[r][0], f0, f1);
        unpack2(acc[r][1], f2, f3);
        float4 o;
        o.x = g * (f0 + bb) + xr.x;
        o.y = g * (f1 + bb) + xr.y;
        o.z = g * (f2 + bb) + xr.z;
        o.w = g * (f3 + bb) + xr.w;
        *(float4*)(out + idx) = o;
    }
}

// ---------------- launcher ----------------
extern "C" void kernel_launch(void* const* d_in, const int* in_sizes, int n_in,
                              void* d_out, int out_size)
{
    const float* x     = (const float*)d_in[0];
    const float* Wq    = (const float*)d_in[1];
    const float* bq    = (const float*)d_in[2];
    const float* Wk    = (const float*)d_in[3];
    const float* bk    = (const float*)d_in[4];
    const float* Wv    = (const float*)d_in[5];
    const float* bv    = (const float*)d_in[6];
    const float* Wo    = (const float*)d_in[7];
    const float* bo    = (const float*)d_in[8];
    const float* gamma = (const float*)d_in[9];
    float* out = (float*)d_out;

    cudaFuncSetAttribute(vproj_kernel,   cudaFuncAttributeMaxDynamicSharedMemorySize, GP_BYTES);
    cudaFuncSetAttribute(outproj_kernel, cudaFuncAttributeMaxDynamicSharedMemorySize, GP_BYTES);

    qkproj_kernel<<<dim3(Nn / 128, Bb), 128>>>(x, Wq, bq, Wk, bk);
    vproj_kernel <<<dim3(Nn / 64, Cc / 64, Bb), 256, GP_BYTES>>>(x, Wv, bv);
    attn_kernel  <<<dim3(Nn / BM, Bb), 256>>>();
    outproj_kernel<<<dim3(Nn / 64, Cc / 64, Bb), 256, GP_BYTES>>>(x, Wo, bo, gamma, out);
}

// round 5
// speedup vs baseline: 3.5512x; 2.1750x over previous
#include <cuda_runtime.h>
#include <cuda_bf16.h>
#include <cstdint>

#define Bb 8
#define Cc 256
#define Nn 4096
#define Dd 16
#define BM 64
#define BN 64
#define NTILES (Nn / BN)

typedef unsigned long long ull;

// ---------------- scratch ----------------
__device__ __nv_bfloat16 g_Qb[(size_t)Bb * Nn * Dd];   // [B,N,16] bf16, (q+bq)*0.25
__device__ __nv_bfloat16 g_Kb[(size_t)Bb * Dd * Nn];   // [B,16,N] bf16, k+bk
__device__ __nv_bfloat16 g_VT[(size_t)Bb * Nn * Cc];   // [B,N,C] bf16
__device__ float g_OA[(size_t)Bb * Cc * Nn];           // [B,C,N]

// ---------------- f32x2 helpers ----------------
static __device__ __forceinline__ ull pack2(float x, float y) {
    ull r; asm("mov.b64 %0, {%1,%2};" : "=l"(r) : "f"(x), "f"(y)); return r;
}
static __device__ __forceinline__ void unpack2(ull v, float &x, float &y) {
    asm("mov.b64 {%0,%1}, %2;" : "=f"(x), "=f"(y) : "l"(v));
}
static __device__ __forceinline__ void ffma2(ull &acc, ull a, ull b) {
    asm("fma.rn.f32x2 %0, %1, %2, %0;" : "+l"(acc) : "l"(a), "l"(b));
}

// ---------------- mma / ldmatrix / cp.async ----------------
static __device__ __forceinline__ uint32_t smem_u32(const void* p) {
    uint32_t a;
    asm("{ .reg .u64 t; cvta.to.shared.u64 t, %1; cvt.u32.u64 %0, t; }" : "=r"(a) : "l"(p));
    return a;
}
static __device__ __forceinline__ void ldsm_x4(uint32_t &r0, uint32_t &r1, uint32_t &r2, uint32_t &r3, uint32_t addr) {
    asm volatile("ldmatrix.sync.aligned.m8n8.x4.shared.b16 {%0,%1,%2,%3}, [%4];"
                 : "=r"(r0), "=r"(r1), "=r"(r2), "=r"(r3) : "r"(addr));
}
static __device__ __forceinline__ void ldsm_x4t(uint32_t &r0, uint32_t &r1, uint32_t &r2, uint32_t &r3, uint32_t addr) {
    asm volatile("ldmatrix.sync.aligned.m8n8.x4.trans.shared.b16 {%0,%1,%2,%3}, [%4];"
                 : "=r"(r0), "=r"(r1), "=r"(r2), "=r"(r3) : "r"(addr));
}
static __device__ __forceinline__ void mma16816(float* d, const uint32_t* a, uint32_t b0, uint32_t b1) {
    asm volatile("mma.sync.aligned.m16n8k16.row.col.f32.bf16.bf16.f32 "
                 "{%0,%1,%2,%3}, {%4,%5,%6,%7}, {%8,%9}, {%0,%1,%2,%3};"
                 : "+f"(d[0]), "+f"(d[1]), "+f"(d[2]), "+f"(d[3])
                 : "r"(a[0]), "r"(a[1]), "r"(a[2]), "r"(a[3]), "r"(b0), "r"(b1));
}
static __device__ __forceinline__ void cp16(uint32_t dst, const void* src) {
    asm volatile("cp.async.cg.shared.global [%0], [%1], 16;" :: "r"(dst), "l"(src));
}
#define CP_COMMIT asm volatile("cp.async.commit_group;" ::: "memory")
#define CP_WAIT1  asm volatile("cp.async.wait_group 1;" ::: "memory")

// ---------------- q/k projection -> bf16 ----------------
__global__ __launch_bounds__(128) void qkproj_kernel(
    const float* __restrict__ x,
    const float* __restrict__ Wq, const float* __restrict__ bq,
    const float* __restrict__ Wk, const float* __restrict__ bk)
{
    __shared__ __align__(16) float wq[Cc * Dd];
    __shared__ __align__(16) float wk[Cc * Dd];
    int t = threadIdx.x;
    for (int i = t; i < Cc * Dd; i += 128) {
        int d = i >> 8, c = i & 255;
        wq[c * 16 + d] = Wq[i];
        wk[c * 16 + d] = Wk[i];
    }
    __syncthreads();
    int b = blockIdx.y;
    int n = blockIdx.x * 128 + t;

    ull qa[8], ka[8];
#pragma unroll
    for (int j = 0; j < 8; j++) { qa[j] = 0ull; ka[j] = 0ull; }
    const float* xp = x + (size_t)b * Cc * Nn + n;
#pragma unroll 4
    for (int c = 0; c < Cc; c++) {
        float xv = xp[(size_t)c * Nn];
        ull xx = pack2(xv, xv);
        const ulonglong2* wqp = (const ulonglong2*)(wq + c * 16);
        const ulonglong2* wkp = (const ulonglong2*)(wk + c * 16);
#pragma unroll
        for (int j = 0; j < 4; j++) {
            ulonglong2 a = wqp[j];
            ffma2(qa[2 * j], xx, a.x);
            ffma2(qa[2 * j + 1], xx, a.y);
            ulonglong2 kk2 = wkp[j];
            ffma2(ka[2 * j], xx, kk2.x);
            ffma2(ka[2 * j + 1], xx, kk2.y);
        }
    }
    float q[16], k[16];
#pragma unroll
    for (int j = 0; j < 8; j++) { unpack2(qa[j], q[2 * j], q[2 * j + 1]); unpack2(ka[j], k[2 * j], k[2 * j + 1]); }
    // Q bf16 with scale 0.25 and bias folded
    uint4 qo[2];
    __nv_bfloat16* qh = (__nv_bfloat16*)qo;
#pragma unroll
    for (int d = 0; d < 16; d++) qh[d] = __float2bfloat16((q[d] + bq[d]) * 0.25f);
    uint4* qdst = (uint4*)(g_Qb + ((size_t)b * Nn + n) * Dd);
    qdst[0] = qo[0]; qdst[1] = qo[1];
#pragma unroll
    for (int d = 0; d < 16; d++)
        g_Kb[((size_t)b * Dd + d) * Nn + n] = __float2bfloat16(k[d] + bk[d]);
}

// ---------------- GEMM smem layout (vproj/outproj) ----------------
#define GP_WD 0
#define GP_XT 33280
#define GP_BYTES (33280 + 17408)

// ---------------- V projection -> bf16 g_VT[B,N,C] ----------------
__global__ __launch_bounds__(256) void vproj_kernel(
    const float* __restrict__ x,
    const float* __restrict__ Wv, const float* __restrict__ bv)
{
    extern __shared__ __align__(16) char gsm[];
    float2* Wd = (float2*)(gsm + GP_WD);
    float*  Xt = (float*)(gsm + GP_XT);
    int t = threadIdx.x, tr = t >> 4, tc = t & 15;
    int n0 = blockIdx.x * 64, m0 = blockIdx.y * 64, b = blockIdx.z;

    ull acc[4][2];
#pragma unroll
    for (int r = 0; r < 4; r++) { acc[r][0] = 0ull; acc[r][1] = 0ull; }

    for (int kc = 0; kc < 4; kc++) {
        int k0 = kc * 64;
        __syncthreads();
#pragma unroll
        for (int l = 0; l < 16; l++) {
            int flat = t + l * 256;
            int rr = flat >> 6, kk = flat & 63;
            float w = Wv[(m0 + rr) * Cc + k0 + kk];
            Wd[kk * 65 + rr] = make_float2(w, w);
            Xt[rr * 68 + kk] = x[((size_t)(b * Cc + k0 + rr)) * Nn + n0 + kk];
        }
        __syncthreads();
#pragma unroll 4
        for (int kk = 0; kk < 64; kk++) {
            ulonglong2 xv = *(const ulonglong2*)(Xt + kk * 68 + tc * 4);
            const ull* wp = (const ull*)(Wd + kk * 65 + tr * 4);
#pragma unroll
            for (int r = 0; r < 4; r++) {
                ull w2 = wp[r];
                ffma2(acc[r][0], w2, xv.x);
                ffma2(acc[r][1], w2, xv.y);
            }
        }
    }
    float f[4][4];
#pragma unroll
    for (int r = 0; r < 4; r++) {
        float bb = bv[m0 + tr * 4 + r];
        unpack2(acc[r][0], f[r][0], f[r][1]);
        unpack2(acc[r][1], f[r][2], f[r][3]);
#pragma unroll
        for (int i = 0; i < 4; i++) f[r][i] += bb;
    }
    __syncthreads();
    __nv_bfloat16* Tb = (__nv_bfloat16*)(gsm + GP_XT);
#pragma unroll
    for (int i = 0; i < 4; i++) {
        __nv_bfloat162 p0 = __floats2bfloat162_rn(f[0][i], f[1][i]);
        __nv_bfloat162 p1 = __floats2bfloat162_rn(f[2][i], f[3][i]);
        *(__nv_bfloat162*)(Tb + (tc * 4 + i) * 72 + tr * 4)     = p0;
        *(__nv_bfloat162*)(Tb + (tc * 4 + i) * 72 + tr * 4 + 2) = p1;
    }
    __syncthreads();
    {
        int n = t >> 2, c = t & 3;
        const uint4* src = (const uint4*)(Tb + n * 72 + c * 16);
        uint4* dst = (uint4*)(g_VT + ((size_t)(b * Nn + n0 + n)) * Cc + m0 + c * 16);
        dst[0] = src[0];
        dst[1] = src[1];
    }
}

// ---------------- fused attention: all-MMA FA2, P in registers ----------------
// dyn smem: VS 2x(64x528)=67584 | KS 2x(16x144)=4608 @67584 | QS 64x48=3072 @72192
#define AT_VS 0
#define AT_KS 67584
#define AT_QS 72192
#define AT_BYTES 75264

__global__ __launch_bounds__(256, 2) void attn_kernel()
{
    extern __shared__ __align__(16) char sm[];
    uint32_t smU = smem_u32(sm);
    int t = threadIdx.x, b = blockIdx.y, m0 = blockIdx.x * BM;
    int wid = t >> 5, lane = t & 31;
    int mg = wid & 3, eg = wid >> 2;

    const char* vb = (const char*)(g_VT + (size_t)b * Nn * Cc);
    const char* kb = (const char*)(g_Kb + (size_t)b * Dd * Nn);
    const char* qb = (const char*)(g_Qb + ((size_t)b * Nn + m0) * Dd);

    int vj = t >> 2, vc = t & 3;
    int kd = t >> 3, kc = t & 7;

    // prologue: stage 0 (+Q), stage 1
#pragma unroll
    for (int st = 0; st < 2; st++) {
        int n0 = st * BN;
        uint32_t dst = smU + AT_VS + st * 33792 + vj * 528 + vc * 16;
        const char* src = vb + ((size_t)(n0 + vj)) * 512 + vc * 16;
#pragma unroll
        for (int u = 0; u < 8; u++) cp16(dst + u * 64, src + u * 64);
        if (t < 128) cp16(smU + AT_KS + st * 2304 + kd * 144 + kc * 16,
                          kb + (size_t)kd * (Nn * 2) + n0 * 2 + kc * 16);
        if (st == 0 && t < 128) {
            int m = t >> 1, c = t & 1;
            cp16(smU + AT_QS + m * 48 + c * 16, qb + m * 32 + c * 16);
        }
        CP_COMMIT;
    }

    float acc[16][4];
#pragma unroll
    for (int i = 0; i < 16; i++)
#pragma unroll
        for (int j = 0; j < 4; j++) acc[i][j] = 0.f;

    uint32_t qa[4];
    float rs0 = 0.f, rs1 = 0.f;

    for (int it = 0; it < NTILES; it++) {
        int s = it & 1;
        CP_WAIT1;
        __syncthreads();
        if (it == 0) {
            uint32_t qaddr = smU + AT_QS +
                (mg * 16 + (lane & 7) + ((lane >> 3) & 1) * 8) * 48 + (lane >> 4) * 16;
            ldsm_x4(qa[0], qa[1], qa[2], qa[3], qaddr);
        }
        // ---- QK via mma: c[8 n-blocks][4]
        float c[8][4];
#pragma unroll
        for (int i = 0; i < 8; i++)
#pragma unroll
            for (int j = 0; j < 4; j++) c[i][j] = 0.f;
#pragma unroll
        for (int nb2 = 0; nb2 < 4; nb2++) {
            uint32_t b0, b1, b2, b3;
            uint32_t ka = smU + AT_KS + s * 2304 + (lane & 15) * 144 +
                          (nb2 * 16 + (lane >> 4) * 8) * 2;
            ldsm_x4t(b0, b1, b2, b3, ka);
            mma16816(c[nb2 * 2],     qa, b0, b1);
            mma16816(c[nb2 * 2 + 1], qa, b2, b3);
        }
        // ---- exp + pack P a-frags
        uint32_t pa[4][4];
#pragma unroll
        for (int kg = 0; kg < 4; kg++) {
#pragma unroll
            for (int hh = 0; hh < 2; hh++) {
                float* cb = c[kg * 2 + hh];
                float e0 = __expf(fminf(fmaxf(cb[0], -50.f), 50.f));
                float e1 = __expf(fminf(fmaxf(cb[1], -50.f), 50.f));
                float e2 = __expf(fminf(fmaxf(cb[2], -50.f), 50.f));
                float e3 = __expf(fminf(fmaxf(cb[3], -50.f), 50.f));
                rs0 += e0 + e1;
                rs1 += e2 + e3;
                __nv_bfloat162 lo = __floats2bfloat162_rn(e0, e1);
                __nv_bfloat162 hi = __floats2bfloat162_rn(e2, e3);
                pa[kg][hh * 2]     = *(uint32_t*)&lo;
                pa[kg][hh * 2 + 1] = *(uint32_t*)&hi;
            }
        }
        // ---- PV via mma: warp covers m16 x e128
#pragma unroll
        for (int kg = 0; kg < 4; kg++) {
#pragma unroll
            for (int eb2 = 0; eb2 < 8; eb2++) {
                uint32_t b0, b1, b2, b3;
                uint32_t va = smU + AT_VS + s * 33792 + (kg * 16 + (lane & 15)) * 528 +
                              (eg * 128 + eb2 * 16 + (lane >> 4) * 8) * 2;
                ldsm_x4t(b0, b1, b2, b3, va);
                mma16816(acc[eb2 * 2],     pa[kg], b0, b1);
                mma16816(acc[eb2 * 2 + 1], pa[kg], b2, b3);
            }
        }
        __syncthreads();
        if (it + 2 < NTILES) {
            int n0 = (it + 2) * BN;
            uint32_t dst = smU + AT_VS + s * 33792 + vj * 528 + vc * 16;
            const char* src = vb + ((size_t)(n0 + vj)) * 512 + vc * 16;
#pragma unroll
            for (int u = 0; u < 8; u++) cp16(dst + u * 64, src + u * 64);
            if (t < 128) cp16(smU + AT_KS + s * 2304 + kd * 144 + kc * 16,
                              kb + (size_t)kd * (Nn * 2) + n0 * 2 + kc * 16);
        }
        CP_COMMIT;
    }

    // rsum reduce across the 4 lanes of each row group
    rs0 += __shfl_xor_sync(0xffffffffu, rs0, 1);
    rs0 += __shfl_xor_sync(0xffffffffu, rs0, 2);
    rs1 += __shfl_xor_sync(0xffffffffu, rs1, 1);
    rs1 += __shfl_xor_sync(0xffffffffu, rs1, 2);
    float inv0 = 1.f / rs0, inv1 = 1.f / rs1;

    int r = lane >> 2, q = lane & 3;
    int mrow = m0 + mg * 16 + r;
    float* ob = g_OA + (size_t)b * Cc * Nn;
#pragma unroll
    for (int eb = 0; eb < 16; eb++) {
        int e = eg * 128 + eb * 8 + 2 * q;
        float* p0 = ob + (size_t)e * Nn;
        p0[mrow]          = acc[eb][0] * inv0;
        p0[Nn + mrow]     = acc[eb][1] * inv0;
        p0[mrow + 8]      = acc[eb][2] * inv1;
        p0[Nn + mrow + 8] = acc[eb][3] * inv1;
    }
}

// ---------------- output projection + residual ----------------
__global__ __launch_bounds__(256) void outproj_kernel(
    const float* __restrict__ x,
    const float* __restrict__ Wo, const float* __restrict__ bo,
    const float* __restrict__ gamma, float* __restrict__ out)
{
    extern __shared__ __align__(16) char gsm[];
    float2* Wd = (float2*)(gsm + GP_WD);
    float*  Xt = (float*)(gsm + GP_XT);
    int t = threadIdx.x, tr = t >> 4, tc = t & 15;
    int n0 = blockIdx.x * 64, m0 = blockIdx.y * 64, b = blockIdx.z;

    ull acc[4][2];
#pragma unroll
    for (int r = 0; r < 4; r++) { acc[r][0] = 0ull; acc[r][1] = 0ull; }

    for (int kc = 0; kc < 4; kc++) {
        int k0 = kc * 64;
        __syncthreads();
#pragma unroll
        for (int l = 0; l < 16; l++) {
            int flat = t + l * 256;
            int rr = flat >> 6, kk = flat & 63;
            float w = Wo[(m0 + rr) * Cc + k0 + kk];
            Wd[kk * 65 + rr] = make_float2(w, w);
            Xt[rr * 68 + kk] = g_OA[((size_t)(b * Cc + k0 + rr)) * Nn + n0 + kk];
        }
        __syncthreads();
#pragma unroll 4
        for (int kk = 0; kk < 64; kk++) {
            ulonglong2 xv = *(const ulonglong2*)(Xt + kk * 68 + tc * 4);
            const ull* wp = (const ull*)(Wd + kk * 65 + tr * 4);
#pragma unroll
            for (int r = 0; r < 4; r++) {
                ull w2 = wp[r];
                ffma2(acc[r][0], w2, xv.x);
                ffma2(acc[r][1], w2, xv.y);
            }
        }
    }
    float g = fminf(fmaxf(gamma[0], 0.f), 1.f);
#pragma unroll
    for (int r = 0; r < 4; r++) {
        int m = m0 + tr * 4 + r;
        float bb = bo[m];
        size_t idx = ((size_t)(b * Cc + m)) * Nn + n0 + tc * 4;
        float4 xr = *(const float4*)(x + idx);
        float f0, f1, f2, f3;
        unpack2(acc[r][0], f0, f1);
        unpack2(acc[r][1], f2, f3);
        float4 o;
        o.x = g * (f0 + bb) + xr.x;
        o.y = g * (f1 + bb) + xr.y;
        o.z = g * (f2 + bb) + xr.z;
        o.w = g * (f3 + bb) + xr.w;
        *(float4*)(out + idx) = o;
    }
}

// ---------------- launcher ----------------
extern "C" void kernel_launch(void* const* d_in, const int* in_sizes, int n_in,
                              void* d_out, int out_size)
{
    const float* x     = (const float*)d_in[0];
    const float* Wq    = (const float*)d_in[1];
    const float* bq    = (const float*)d_in[2];
    const float* Wk    = (const float*)d_in[3];
    const float* bk    = (const float*)d_in[4];
    const float* Wv    = (const float*)d_in[5];
    const float* bv    = (const float*)d_in[6];
    const float* Wo    = (const float*)d_in[7];
    const float* bo    = (const float*)d_in[8];
    const float* gamma = (const float*)d_in[9];
    float* out = (float*)d_out;

    cudaFuncSetAttribute(vproj_kernel,   cudaFuncAttributeMaxDynamicSharedMemorySize, GP_BYTES);
    cudaFuncSetAttribute(outproj_kernel, cudaFuncAttributeMaxDynamicSharedMemorySize, GP_BYTES);
    cudaFuncSetAttribute(attn_kernel,    cudaFuncAttributeMaxDynamicSharedMemorySize, AT_BYTES);

    qkproj_kernel<<<dim3(Nn / 128, Bb), 128>>>(x, Wq, bq, Wk, bk);
    vproj_kernel <<<dim3(Nn / 64, Cc / 64, Bb), 256, GP_BYTES>>>(x, Wv, bv);
    attn_kernel  <<<dim3(Nn / BM, Bb), 256, AT_BYTES>>>();
    outproj_kernel<<<dim3(Nn / 64, Cc / 64, Bb), 256, GP_BYTES>>>(x, Wo, bo, gamma, out);
}

// round 7
// speedup vs baseline: 6.0946x; 1.7162x over previous
#include <cuda_runtime.h>
#include <cuda_bf16.h>
#include <cstdint>

#define Bb 8
#define Cc 256
#define Nn 4096
#define Dd 16
#define BM 128
#define BN 64
#define NTILES (Nn / BN)

typedef unsigned long long ull;

// ---------------- scratch ----------------
__device__ __nv_bfloat16 g_Qb[(size_t)Bb * Nn * Dd];   // [B,N,16] bf16, (q+bq)*0.25
__device__ __nv_bfloat16 g_Kb[(size_t)Bb * Dd * Nn];   // [B,16,N] bf16, k+bk
__device__ __nv_bfloat16 g_VT[(size_t)Bb * Nn * Cc];   // [B,N,C] bf16
__device__ float g_OA[(size_t)Bb * Cc * Nn];           // [B,C,N]

// ---------------- helpers ----------------
static __device__ __forceinline__ uint32_t smem_u32(const void* p) {
    uint32_t a;
    asm("{ .reg .u64 t; cvta.to.shared.u64 t, %1; cvt.u32.u64 %0, t; }" : "=r"(a) : "l"(p));
    return a;
}
static __device__ __forceinline__ void ldsm_x4(uint32_t &r0, uint32_t &r1, uint32_t &r2, uint32_t &r3, uint32_t addr) {
    asm volatile("ldmatrix.sync.aligned.m8n8.x4.shared.b16 {%0,%1,%2,%3}, [%4];"
                 : "=r"(r0), "=r"(r1), "=r"(r2), "=r"(r3) : "r"(addr));
}
static __device__ __forceinline__ void ldsm_x4t(uint32_t &r0, uint32_t &r1, uint32_t &r2, uint32_t &r3, uint32_t addr) {
    asm volatile("ldmatrix.sync.aligned.m8n8.x4.trans.shared.b16 {%0,%1,%2,%3}, [%4];"
                 : "=r"(r0), "=r"(r1), "=r"(r2), "=r"(r3) : "r"(addr));
}
static __device__ __forceinline__ void mma16816(float* d, const uint32_t* a, uint32_t b0, uint32_t b1) {
    asm volatile("mma.sync.aligned.m16n8k16.row.col.f32.bf16.bf16.f32 "
                 "{%0,%1,%2,%3}, {%4,%5,%6,%7}, {%8,%9}, {%0,%1,%2,%3};"
                 : "+f"(d[0]), "+f"(d[1]), "+f"(d[2]), "+f"(d[3])
                 : "r"(a[0]), "r"(a[1]), "r"(a[2]), "r"(a[3]), "r"(b0), "r"(b1));
}
static __device__ __forceinline__ void mma_tf32(float* d, const uint32_t* a, uint32_t b0, uint32_t b1) {
    asm volatile("mma.sync.aligned.m16n8k8.row.col.f32.tf32.tf32.f32 "
                 "{%0,%1,%2,%3}, {%4,%5,%6,%7}, {%8,%9}, {%0,%1,%2,%3};"
                 : "+f"(d[0]), "+f"(d[1]), "+f"(d[2]), "+f"(d[3])
                 : "r"(a[0]), "r"(a[1]), "r"(a[2]), "r"(a[3]), "r"(b0), "r"(b1));
}
static __device__ __forceinline__ uint32_t cvt_tf32(float f) {
    uint32_t r; asm("cvt.rna.tf32.f32 %0, %1;" : "=r"(r) : "f"(f)); return r;
}
static __device__ __forceinline__ void cp16(uint32_t dst, const void* src) {
    asm volatile("cp.async.cg.shared.global [%0], [%1], 16;" :: "r"(dst), "l"(src));
}
#define CP_COMMIT asm volatile("cp.async.commit_group;" ::: "memory")
#define CP_WAIT1  asm volatile("cp.async.wait_group 1;" ::: "memory")

// ================= fused projection: V (+Q,K) via tf32 MMA =================
// smem: W 2 stages [128][36]f = 36864 | X 2 stages [32][136]f = 34816 @36864
#define PJ_WS 0
#define PJ_XS 36864
#define PJ_BYTES 71680

__global__ __launch_bounds__(256, 2) void proj_kernel(
    const float* __restrict__ x,
    const float* __restrict__ Wq, const float* __restrict__ bq,
    const float* __restrict__ Wk, const float* __restrict__ bk,
    const float* __restrict__ Wv, const float* __restrict__ bv)
{
    extern __shared__ __align__(16) char sm[];
    uint32_t smU = smem_u32(sm);
    int t = threadIdx.x, wid = t >> 5, lane = t & 31;
    int mg = wid >> 1, ng = wid & 1;
    int n0 = blockIdx.x * 128, ytile = blockIdx.y, b = blockIdx.z;
    bool active = (ytile < 2) || (mg == 0);

    // W source row pointer for this thread's cp row (m = t>>1)
    int wm = t >> 1, wq4 = t & 1;
    const float* wsrc;
    bool wvalid = true;
    if (ytile < 2) wsrc = Wv + (ytile * 128 + wm) * Cc;
    else {
        if (wm < 16) wsrc = Wq + wm * Cc;
        else if (wm < 32) wsrc = Wk + (wm - 16) * Cc;
        else { wsrc = Wq; wvalid = false; }
    }
    const float* xb = x + (size_t)b * Cc * Nn + n0;
    int xk = t >> 3, xn = t & 7;

    // prologue: chunks 0,1
#pragma unroll
    for (int ch = 0; ch < 2; ch++) {
        int k0 = ch * 32, st = ch & 1;
        if (wvalid) {
#pragma unroll
            for (int u = 0; u < 4; u++) {
                int kq = wq4 + 2 * u;
                cp16(smU + PJ_WS + st * 18432 + wm * 144 + kq * 16, wsrc + k0 + kq * 4);
            }
        }
#pragma unroll
        for (int u = 0; u < 4; u++) {
            int nq = xn + 8 * u;
            cp16(smU + PJ_XS + st * 17408 + xk * 544 + nq * 16, xb + (size_t)(k0 + xk) * Nn + nq * 4);
        }
        CP_COMMIT;
    }

    float acc[2][8][4];
#pragma unroll
    for (int i = 0; i < 2; i++)
#pragma unroll
        for (int j = 0; j < 8; j++)
#pragma unroll
            for (int q = 0; q < 4; q++) acc[i][j][q] = 0.f;

    for (int ch = 0; ch < 8; ch++) {
        int st = ch & 1;
        CP_WAIT1;
        __syncthreads();
        if (active) {
            const float* wb = (const float*)(sm + PJ_WS + st * 18432);
            const float* xs = (const float*)(sm + PJ_XS + st * 17408);
#pragma unroll
            for (int k8 = 0; k8 < 4; k8++) {
                uint32_t A[2][4];
#pragma unroll
                for (int mi = 0; mi < 2; mi++) {
                    const float* ap = wb + (mg * 32 + mi * 16 + (lane >> 2)) * 36 + k8 * 8 + (lane & 3);
                    A[mi][0] = cvt_tf32(ap[0]);
                    A[mi][2] = cvt_tf32(ap[4]);
                    A[mi][1] = cvt_tf32(ap[8 * 36]);
                    A[mi][3] = cvt_tf32(ap[8 * 36 + 4]);
                }
                const float* bp = xs + (k8 * 8 + (lane & 3)) * 136 + ng * 64 + (lane >> 2);
#pragma unroll
                for (int nb = 0; nb < 8; nb++) {
                    uint32_t b0 = cvt_tf32(bp[nb * 8]);
                    uint32_t b1 = cvt_tf32(bp[nb * 8 + 4 * 136]);
                    mma_tf32(acc[0][nb], A[0], b0, b1);
                    mma_tf32(acc[1][nb], A[1], b0, b1);
                }
            }
        }
        __syncthreads();
        if (ch + 2 < 8) {
            int k0 = (ch + 2) * 32;
            if (wvalid) {
#pragma unroll
                for (int u = 0; u < 4; u++) {
                    int kq = wq4 + 2 * u;
                    cp16(smU + PJ_WS + st * 18432 + wm * 144 + kq * 16, wsrc + k0 + kq * 4);
                }
            }
#pragma unroll
            for (int u = 0; u < 4; u++) {
                int nq = xn + 8 * u;
                cp16(smU + PJ_XS + st * 17408 + xk * 544 + nq * 16, xb + (size_t)(k0 + xk) * Nn + nq * 4);
            }
        }
        CP_COMMIT;
    }
    __syncthreads();  // all LDS done before smem reuse

    if (ytile < 2) {
        // V epilogue: stage bf16 transposed [n 128][m pad 136]
        __nv_bfloat16* Tb = (__nv_bfloat16*)(sm + PJ_XS);
#pragma unroll
        for (int mi = 0; mi < 2; mi++) {
            int m = mg * 32 + mi * 16 + (lane >> 2);
            float bv0 = bv[ytile * 128 + m];
            float bv1 = bv[ytile * 128 + m + 8];
#pragma unroll
            for (int nb = 0; nb < 8; nb++) {
                int n = ng * 64 + nb * 8 + (lane & 3) * 2;
                float* a = acc[mi][nb];
                Tb[(size_t)n * 136 + m]           = __float2bfloat16(a[0] + bv0);
                Tb[(size_t)(n + 1) * 136 + m]     = __float2bfloat16(a[1] + bv0);
                Tb[(size_t)n * 136 + m + 8]       = __float2bfloat16(a[2] + bv1);
                Tb[(size_t)(n + 1) * 136 + m + 8] = __float2bfloat16(a[3] + bv1);
            }
        }
        __syncthreads();
        // FIXED: copy the FULL 128-half (256B) row half per (n,c): 8 x 16B chunks
        int n = t >> 1, c = t & 1;
        const uint4* src = (const uint4*)((const char*)Tb + n * 272 + c * 128);
        uint4* dst = (uint4*)((char*)(g_VT + ((size_t)(b * Nn + n0 + n)) * Cc + ytile * 128) + c * 128);
#pragma unroll
        for (int u = 0; u < 8; u++) dst[u] = src[u];
    } else {
        // Q/K epilogue (mg==0 holds rows 0..31)
        __nv_bfloat16* Qt = (__nv_bfloat16*)(sm + PJ_XS);            // [128][24]
        __nv_bfloat16* Kt = (__nv_bfloat16*)(sm + PJ_XS + 6144);     // [16][136]
        if (mg == 0) {
            // mi=0: Q rows 0..15
            {
                int d = lane >> 2;
                float b0 = bq[d], b1 = bq[d + 8];
#pragma unroll
                for (int nb = 0; nb < 8; nb++) {
                    int n = ng * 64 + nb * 8 + (lane & 3) * 2;
                    float* a = acc[0][nb];
                    Qt[(size_t)n * 24 + d]           = __float2bfloat16((a[0] + b0) * 0.25f);
                    Qt[(size_t)(n + 1) * 24 + d]     = __float2bfloat16((a[1] + b0) * 0.25f);
                    Qt[(size_t)n * 24 + d + 8]       = __float2bfloat16((a[2] + b1) * 0.25f);
                    Qt[(size_t)(n + 1) * 24 + d + 8] = __float2bfloat16((a[3] + b1) * 0.25f);
                }
            }
            // mi=1: K rows 0..15
            {
                int d = lane >> 2;
                float b0 = bk[d], b1 = bk[d + 8];
#pragma unroll
                for (int nb = 0; nb < 8; nb++) {
                    int n = ng * 64 + nb * 8 + (lane & 3) * 2;
                    float* a = acc[1][nb];
                    Kt[(size_t)d * 136 + n]           = __float2bfloat16(a[0] + b0);
                    Kt[(size_t)d * 136 + n + 1]       = __float2bfloat16(a[1] + b0);
                    Kt[(size_t)(d + 8) * 136 + n]     = __float2bfloat16(a[2] + b1);
                    Kt[(size_t)(d + 8) * 136 + n + 1] = __float2bfloat16(a[3] + b1);
                }
            }
        }
        __syncthreads();
        {
            int n = t >> 1, c = t & 1;
            const uint4* src = (const uint4*)((const char*)Qt + n * 48 + c * 16);
            uint4* dst = (uint4*)((char*)(g_Qb + ((size_t)(b * Nn + n0 + n)) * Dd) + c * 16);
            dst[0] = src[0];
        }
        {
            int d = t >> 4, c = t & 15;
            const uint4* src = (const uint4*)((const char*)Kt + d * 272 + c * 16);
            uint4* dst = (uint4*)((char*)(g_Kb + ((size_t)(b * Dd + d)) * Nn + n0) + c * 16);
            dst[0] = src[0];
        }
    }
}

// ================= fused attention: all-MMA FA2, BM=128 =================
// smem: VS 2x(64x528)=67584 | KS 2x(16x144)=4608 @67584 | QS 128x48 @72192
#define AT_VS 0
#define AT_KS 67584
#define AT_QS 72192
#define AT_BYTES 78336

__global__ __launch_bounds__(512, 1) void attn_kernel()
{
    extern __shared__ __align__(16) char sm[];
    uint32_t smU = smem_u32(sm);
    int t = threadIdx.x, b = blockIdx.y, m0 = blockIdx.x * BM;
    int wid = t >> 5, lane = t & 31;
    int mg = wid >> 1, eg = wid & 1;

    const char* vb = (const char*)(g_VT + (size_t)b * Nn * Cc);
    const char* kb = (const char*)(g_Kb + (size_t)b * Dd * Nn);
    const char* qb = (const char*)(g_Qb + ((size_t)b * Nn + m0) * Dd);

    int vj = t >> 3, vc = t & 7;
    int kd = t >> 3, kc = t & 7;

#pragma unroll
    for (int st = 0; st < 2; st++) {
        int n0 = st * BN;
        uint32_t dst = smU + AT_VS + st * 33792 + vj * 528 + vc * 16;
        const char* src = vb + ((size_t)(n0 + vj)) * 512 + vc * 16;
#pragma unroll
        for (int u = 0; u < 4; u++) cp16(dst + u * 128, src + u * 128);
        if (t < 128) cp16(smU + AT_KS + st * 2304 + kd * 144 + kc * 16,
                          kb + (size_t)kd * (Nn * 2) + n0 * 2 + kc * 16);
        if (st == 0 && t < 256) {
            int m = t >> 1, c = t & 1;
            cp16(smU + AT_QS + m * 48 + c * 16, qb + m * 32 + c * 16);
        }
        CP_COMMIT;
    }

    float acc[16][4];
#pragma unroll
    for (int i = 0; i < 16; i++)
#pragma unroll
        for (int j = 0; j < 4; j++) acc[i][j] = 0.f;

    uint32_t qa[4];
    float rs0 = 0.f, rs1 = 0.f;

    for (int it = 0; it < NTILES; it++) {
        int s = it & 1;
        CP_WAIT1;
        __syncthreads();
        if (it == 0) {
            uint32_t qaddr = smU + AT_QS +
                (mg * 16 + (lane & 7) + ((lane >> 3) & 1) * 8) * 48 + (lane >> 4) * 16;
            ldsm_x4(qa[0], qa[1], qa[2], qa[3], qaddr);
        }
        // QK (per nb2) -> exp -> pa
        uint32_t pa[4][4];
#pragma unroll
        for (int nb2 = 0; nb2 < 4; nb2++) {
            float c[2][4];
#pragma unroll
            for (int h = 0; h < 2; h++)
#pragma unroll
                for (int j = 0; j < 4; j++) c[h][j] = 0.f;
            uint32_t b0, b1, b2, b3;
            uint32_t ka = smU + AT_KS + s * 2304 + (lane & 15) * 144 +
                          (nb2 * 16 + (lane >> 4) * 8) * 2;
            ldsm_x4t(b0, b1, b2, b3, ka);
            mma16816(c[0], qa, b0, b1);
            mma16816(c[1], qa, b2, b3);
#pragma unroll
            for (int h = 0; h < 2; h++) {
                float e0 = __expf(fminf(fmaxf(c[h][0], -50.f), 50.f));
                float e1 = __expf(fminf(fmaxf(c[h][1], -50.f), 50.f));
                float e2 = __expf(fminf(fmaxf(c[h][2], -50.f), 50.f));
                float e3 = __expf(fminf(fmaxf(c[h][3], -50.f), 50.f));
                rs0 += e0 + e1;
                rs1 += e2 + e3;
                __nv_bfloat162 lo = __floats2bfloat162_rn(e0, e1);
                __nv_bfloat162 hi = __floats2bfloat162_rn(e2, e3);
                pa[nb2][h * 2]     = *(uint32_t*)&lo;
                pa[nb2][h * 2 + 1] = *(uint32_t*)&hi;
            }
        }
        // PV: warp m16 x e128
#pragma unroll
        for (int kg = 0; kg < 4; kg++) {
#pragma unroll
            for (int eb2 = 0; eb2 < 8; eb2++) {
                uint32_t b0, b1, b2, b3;
                uint32_t va = smU + AT_VS + s * 33792 + (kg * 16 + (lane & 15)) * 528 +
                              (eg * 128 + eb2 * 16 + (lane >> 4) * 8) * 2;
                ldsm_x4t(b0, b1, b2, b3, va);
                mma16816(acc[eb2 * 2],     pa[kg], b0, b1);
                mma16816(acc[eb2 * 2 + 1], pa[kg], b2, b3);
            }
        }
        __syncthreads();
        if (it + 2 < NTILES) {
            int n0 = (it + 2) * BN;
            uint32_t dst = smU + AT_VS + s * 33792 + vj * 528 + vc * 16;
            const char* src = vb + ((size_t)(n0 + vj)) * 512 + vc * 16;
#pragma unroll
            for (int u = 0; u < 4; u++) cp16(dst + u * 128, src + u * 128);
            if (t < 128) cp16(smU + AT_KS + s * 2304 + kd * 144 + kc * 16,
                              kb + (size_t)kd * (Nn * 2) + n0 * 2 + kc * 16);
        }
        CP_COMMIT;
    }

    rs0 += __shfl_xor_sync(0xffffffffu, rs0, 1);
    rs0 += __shfl_xor_sync(0xffffffffu, rs0, 2);
    rs1 += __shfl_xor_sync(0xffffffffu, rs1, 1);
    rs1 += __shfl_xor_sync(0xffffffffu, rs1, 2);
    float inv0 = 1.f / rs0, inv1 = 1.f / rs1;

    int r = lane >> 2, q = lane & 3;
    int mrow = m0 + mg * 16 + r;
    float* ob = g_OA + (size_t)b * Cc * Nn;
#pragma unroll
    for (int eb = 0; eb < 16; eb++) {
        int e = eg * 128 + eb * 8 + 2 * q;
        float* p0 = ob + (size_t)e * Nn;
        p0[mrow]          = acc[eb][0] * inv0;
        p0[Nn + mrow]     = acc[eb][1] * inv0;
        p0[mrow + 8]      = acc[eb][2] * inv1;
        p0[Nn + mrow + 8] = acc[eb][3] * inv1;
    }
}

// ================= output projection via tf32 MMA + residual =================
__global__ __launch_bounds__(256, 2) void outproj_kernel(
    const float* __restrict__ x,
    const float* __restrict__ Wo, const float* __restrict__ bo,
    const float* __restrict__ gamma, float* __restrict__ out)
{
    extern __shared__ __align__(16) char sm[];
    uint32_t smU = smem_u32(sm);
    int t = threadIdx.x, wid = t >> 5, lane = t & 31;
    int mg = wid >> 1, ng = wid & 1;
    int n0 = blockIdx.x * 128, ytile = blockIdx.y, b = blockIdx.z;

    int wm = t >> 1, wq4 = t & 1;
    const float* wsrc = Wo + (ytile * 128 + wm) * Cc;
    const float* xb = g_OA + (size_t)b * Cc * Nn + n0;
    int xk = t >> 3, xn = t & 7;

#pragma unroll
    for (int ch = 0; ch < 2; ch++) {
        int k0 = ch * 32, st = ch & 1;
#pragma unroll
        for (int u = 0; u < 4; u++) {
            int kq = wq4 + 2 * u;
            cp16(smU + PJ_WS + st * 18432 + wm * 144 + kq * 16, wsrc + k0 + kq * 4);
        }
#pragma unroll
        for (int u = 0; u < 4; u++) {
            int nq = xn + 8 * u;
            cp16(smU + PJ_XS + st * 17408 + xk * 544 + nq * 16, xb + (size_t)(k0 + xk) * Nn + nq * 4);
        }
        CP_COMMIT;
    }

    float acc[2][8][4];
#pragma unroll
    for (int i = 0; i < 2; i++)
#pragma unroll
        for (int j = 0; j < 8; j++)
#pragma unroll
            for (int q = 0; q < 4; q++) acc[i][j][q] = 0.f;

    for (int ch = 0; ch < 8; ch++) {
        int st = ch & 1;
        CP_WAIT1;
        __syncthreads();
        {
            const float* wb = (const float*)(sm + PJ_WS + st * 18432);
            const float* xs = (const float*)(sm + PJ_XS + st * 17408);
#pragma unroll
            for (int k8 = 0; k8 < 4; k8++) {
                uint32_t A[2][4];
#pragma unroll
                for (int mi = 0; mi < 2; mi++) {
                    const float* ap = wb + (mg * 32 + mi * 16 + (lane >> 2)) * 36 + k8 * 8 + (lane & 3);
                    A[mi][0] = cvt_tf32(ap[0]);
                    A[mi][2] = cvt_tf32(ap[4]);
                    A[mi][1] = cvt_tf32(ap[8 * 36]);
                    A[mi][3] = cvt_tf32(ap[8 * 36 + 4]);
                }
                const float* bp = xs + (k8 * 8 + (lane & 3)) * 136 + ng * 64 + (lane >> 2);
#pragma unroll
                for (int nb = 0; nb < 8; nb++) {
                    uint32_t b0 = cvt_tf32(bp[nb * 8]);
                    uint32_t b1 = cvt_tf32(bp[nb * 8 + 4 * 136]);
                    mma_tf32(acc[0][nb], A[0], b0, b1);
                    mma_tf32(acc[1][nb], A[1], b0, b1);
                }
            }
        }
        __syncthreads();
        if (ch + 2 < 8) {
            int k0 = (ch + 2) * 32;
#pragma unroll
            for (int u = 0; u < 4; u++) {
                int kq = wq4 + 2 * u;
                cp16(smU + PJ_WS + st * 18432 + wm * 144 + kq * 16, wsrc + k0 + kq * 4);
            }
#pragma unroll
            for (int u = 0; u < 4; u++) {
                int nq = xn + 8 * u;
                cp16(smU + PJ_XS + st * 17408 + xk * 544 + nq * 16, xb + (size_t)(k0 + xk) * Nn + nq * 4);
            }
        }
        CP_COMMIT;
    }
    __syncthreads();

    // stage fp32 tile [m 128][n pad 132] for coalesced fused stores
    float* Tf = (float*)sm;
#pragma unroll
    for (int mi = 0; mi < 2; mi++) {
        int m = mg * 32 + mi * 16 + (lane >> 2);
#pragma unroll
        for (int nb = 0; nb < 8; nb++) {
            int n = ng * 64 + nb * 8 + (lane & 3) * 2;
            float* a = acc[mi][nb];
            *(float2*)(Tf + (size_t)m * 132 + n)       = make_float2(a[0], a[1]);
            *(float2*)(Tf + (size_t)(m + 8) * 132 + n) = make_float2(a[2], a[3]);
        }
    }
    __syncthreads();
    float g = fminf(fmaxf(gamma[0], 0.f), 1.f);
    {
        int m = t >> 1, c = t & 1;
        int mglob = ytile * 128 + m;
        float bb = bo[mglob];
        size_t base = ((size_t)(b * Cc + mglob)) * Nn + n0 + c * 64;
#pragma unroll
        for (int u = 0; u < 16; u++) {
            float4 v = *(const float4*)(Tf + (size_t)m * 132 + c * 64 + u * 4);
            float4 xr = *(const float4*)(x + base + u * 4);
            float4 o;
            o.x = g * (v.x + bb) + xr.x;
            o.y = g * (v.y + bb) + xr.y;
            o.z = g * (v.z + bb) + xr.z;
            o.w = g * (v.w + bb) + xr.w;
            *(float4*)(out + base + u * 4) = o;
        }
    }
}

// ---------------- launcher ----------------
extern "C" void kernel_launch(void* const* d_in, const int* in_sizes, int n_in,
                              void* d_out, int out_size)
{
    const float* x     = (const float*)d_in[0];
    const float* Wq    = (const float*)d_in[1];
    const float* bq    = (const float*)d_in[2];
    const float* Wk    = (const float*)d_in[3];
    const float* bk    = (const float*)d_in[4];
    const float* Wv    = (const float*)d_in[5];
    const float* bv    = (const float*)d_in[6];
    const float* Wo    = (const float*)d_in[7];
    const float* bo    = (const float*)d_in[8];
    const float* gamma = (const float*)d_in[9];
    float* out = (float*)d_out;

    cudaFuncSetAttribute(proj_kernel,    cudaFuncAttributeMaxDynamicSharedMemorySize, PJ_BYTES);
    cudaFuncSetAttribute(outproj_kernel, cudaFuncAttributeMaxDynamicSharedMemorySize, PJ_BYTES);
    cudaFuncSetAttribute(attn_kernel,    cudaFuncAttributeMaxDynamicSharedMemorySize, AT_BYTES);

    proj_kernel   <<<dim3(Nn / 128, 3, Bb), 256, PJ_BYTES>>>(x, Wq, bq, Wk, bk, Wv, bv);
    attn_kernel   <<<dim3(Nn / BM, Bb), 512, AT_BYTES>>>();
    outproj_kernel<<<dim3(Nn / 128, 2, Bb), 256, PJ_BYTES>>>(x, Wo, bo, gamma, out);
}

// round 8
// speedup vs baseline: 6.8721x; 1.1276x over previous
#include <cuda_runtime.h>
#include <cuda_bf16.h>
#include <cstdint>

#define Bb 8
#define Cc 256
#define Nn 4096
#define Dd 16
#define BM 128
#define BN 64
#define NTILES (Nn / BN)

typedef unsigned long long ull;

// ---------------- scratch ----------------
__device__ __nv_bfloat16 g_Qb[(size_t)Bb * Nn * Dd];   // [B,N,16] bf16, (q+bq)*0.25*log2e
__device__ __nv_bfloat16 g_Kb[(size_t)Bb * Dd * Nn];   // [B,16,N] bf16, k+bk
__device__ __nv_bfloat16 g_VT[(size_t)Bb * Nn * Cc];   // [B,N,C] bf16
__device__ float g_OA[(size_t)Bb * Cc * Nn];           // [B,C,N]

// ---------------- helpers ----------------
static __device__ __forceinline__ uint32_t smem_u32(const void* p) {
    uint32_t a;
    asm("{ .reg .u64 t; cvta.to.shared.u64 t, %1; cvt.u32.u64 %0, t; }" : "=r"(a) : "l"(p));
    return a;
}
static __device__ __forceinline__ void ldsm_x4(uint32_t &r0, uint32_t &r1, uint32_t &r2, uint32_t &r3, uint32_t addr) {
    asm volatile("ldmatrix.sync.aligned.m8n8.x4.shared.b16 {%0,%1,%2,%3}, [%4];"
                 : "=r"(r0), "=r"(r1), "=r"(r2), "=r"(r3) : "r"(addr));
}
static __device__ __forceinline__ void ldsm_x4t(uint32_t &r0, uint32_t &r1, uint32_t &r2, uint32_t &r3, uint32_t addr) {
    asm volatile("ldmatrix.sync.aligned.m8n8.x4.trans.shared.b16 {%0,%1,%2,%3}, [%4];"
                 : "=r"(r0), "=r"(r1), "=r"(r2), "=r"(r3) : "r"(addr));
}
static __device__ __forceinline__ void mma16816(float* d, const uint32_t* a, uint32_t b0, uint32_t b1) {
    asm volatile("mma.sync.aligned.m16n8k16.row.col.f32.bf16.bf16.f32 "
                 "{%0,%1,%2,%3}, {%4,%5,%6,%7}, {%8,%9}, {%0,%1,%2,%3};"
                 : "+f"(d[0]), "+f"(d[1]), "+f"(d[2]), "+f"(d[3])
                 : "r"(a[0]), "r"(a[1]), "r"(a[2]), "r"(a[3]), "r"(b0), "r"(b1));
}
static __device__ __forceinline__ void mma_tf32(float* d, const uint32_t* a, uint32_t b0, uint32_t b1) {
    asm volatile("mma.sync.aligned.m16n8k8.row.col.f32.tf32.tf32.f32 "
                 "{%0,%1,%2,%3}, {%4,%5,%6,%7}, {%8,%9}, {%0,%1,%2,%3};"
                 : "+f"(d[0]), "+f"(d[1]), "+f"(d[2]), "+f"(d[3])
                 : "r"(a[0]), "r"(a[1]), "r"(a[2]), "r"(a[3]), "r"(b0), "r"(b1));
}
static __device__ __forceinline__ uint32_t cvt_tf32(float f) {
    uint32_t r; asm("cvt.rna.tf32.f32 %0, %1;" : "=r"(r) : "f"(f)); return r;
}
static __device__ __forceinline__ float ex2(float x) {
    float y; asm("ex2.approx.ftz.f32 %0, %1;" : "=f"(y) : "f"(x)); return y;
}
static __device__ __forceinline__ void sts32(uint32_t addr, uint32_t v) {
    asm volatile("st.shared.b32 [%0], %1;" :: "r"(addr), "r"(v));
}
static __device__ __forceinline__ void cp16(uint32_t dst, const void* src) {
    asm volatile("cp.async.cg.shared.global [%0], [%1], 16;" :: "r"(dst), "l"(src));
}
#define CP_COMMIT asm volatile("cp.async.commit_group;" ::: "memory")
#define CP_WAIT1  asm volatile("cp.async.wait_group 1;" ::: "memory")

#define QSCALE 0.36067376022224085f   // 0.25 * log2(e)
#define CLIP2  72.134752f             // 50 * log2(e)

// ================= fused projection: V (+Q,K) via tf32 MMA =================
#define PJ_WS 0
#define PJ_XS 36864
#define PJ_BYTES (36864 + 34816)

__global__ __launch_bounds__(256, 2) void proj_kernel(
    const float* __restrict__ x,
    const float* __restrict__ Wq, const float* __restrict__ bq,
    const float* __restrict__ Wk, const float* __restrict__ bk,
    const float* __restrict__ Wv, const float* __restrict__ bv)
{
    extern __shared__ __align__(16) char sm[];
    uint32_t smU = smem_u32(sm);
    int t = threadIdx.x, wid = t >> 5, lane = t & 31;
    int mg = wid >> 1, ng = wid & 1;
    int n0 = blockIdx.x * 128, ytile = blockIdx.y, b = blockIdx.z;
    bool active = (ytile < 2) || (mg == 0);

    int wm = t >> 1, wq4 = t & 1;
    const float* wsrc;
    bool wvalid = true;
    if (ytile < 2) wsrc = Wv + (ytile * 128 + wm) * Cc;
    else {
        if (wm < 16) wsrc = Wq + wm * Cc;
        else if (wm < 32) wsrc = Wk + (wm - 16) * Cc;
        else { wsrc = Wq; wvalid = false; }
    }
    const float* xb = x + (size_t)b * Cc * Nn + n0;
    int xk = t >> 3, xn = t & 7;

#pragma unroll
    for (int ch = 0; ch < 2; ch++) {
        int k0 = ch * 32, st = ch & 1;
        if (wvalid) {
#pragma unroll
            for (int u = 0; u < 4; u++) {
                int kq = wq4 + 2 * u;
                cp16(smU + PJ_WS + st * 18432 + wm * 144 + kq * 16, wsrc + k0 + kq * 4);
            }
        }
#pragma unroll
        for (int u = 0; u < 4; u++) {
            int nq = xn + 8 * u;
            cp16(smU + PJ_XS + st * 17408 + xk * 544 + nq * 16, xb + (size_t)(k0 + xk) * Nn + nq * 4);
        }
        CP_COMMIT;
    }

    float acc[2][8][4];
#pragma unroll
    for (int i = 0; i < 2; i++)
#pragma unroll
        for (int j = 0; j < 8; j++)
#pragma unroll
            for (int q = 0; q < 4; q++) acc[i][j][q] = 0.f;

    for (int ch = 0; ch < 8; ch++) {
        int st = ch & 1;
        CP_WAIT1;
        __syncthreads();
        if (active) {
            const float* wb = (const float*)(sm + PJ_WS + st * 18432);
            const float* xs = (const float*)(sm + PJ_XS + st * 17408);
#pragma unroll
            for (int k8 = 0; k8 < 4; k8++) {
                uint32_t A[2][4];
#pragma unroll
                for (int mi = 0; mi < 2; mi++) {
                    const float* ap = wb + (mg * 32 + mi * 16 + (lane >> 2)) * 36 + k8 * 8 + (lane & 3);
                    A[mi][0] = cvt_tf32(ap[0]);
                    A[mi][2] = cvt_tf32(ap[4]);
                    A[mi][1] = cvt_tf32(ap[8 * 36]);
                    A[mi][3] = cvt_tf32(ap[8 * 36 + 4]);
                }
                const float* bp = xs + (k8 * 8 + (lane & 3)) * 136 + ng * 64 + (lane >> 2);
#pragma unroll
                for (int nb = 0; nb < 8; nb++) {
                    uint32_t b0 = cvt_tf32(bp[nb * 8]);
                    uint32_t b1 = cvt_tf32(bp[nb * 8 + 4 * 136]);
                    mma_tf32(acc[0][nb], A[0], b0, b1);
                    mma_tf32(acc[1][nb], A[1], b0, b1);
                }
            }
        }
        __syncthreads();
        if (ch + 2 < 8) {
            int k0 = (ch + 2) * 32;
            if (wvalid) {
#pragma unroll
                for (int u = 0; u < 4; u++) {
                    int kq = wq4 + 2 * u;
                    cp16(smU + PJ_WS + st * 18432 + wm * 144 + kq * 16, wsrc + k0 + kq * 4);
                }
            }
#pragma unroll
            for (int u = 0; u < 4; u++) {
                int nq = xn + 8 * u;
                cp16(smU + PJ_XS + st * 17408 + xk * 544 + nq * 16, xb + (size_t)(k0 + xk) * Nn + nq * 4);
            }
        }
        CP_COMMIT;
    }
    __syncthreads();

    if (ytile < 2) {
        __nv_bfloat16* Tb = (__nv_bfloat16*)(sm + PJ_XS);
#pragma unroll
        for (int mi = 0; mi < 2; mi++) {
            int m = mg * 32 + mi * 16 + (lane >> 2);
            float bv0 = bv[ytile * 128 + m];
            float bv1 = bv[ytile * 128 + m + 8];
#pragma unroll
            for (int nb = 0; nb < 8; nb++) {
                int n = ng * 64 + nb * 8 + (lane & 3) * 2;
                float* a = acc[mi][nb];
                Tb[(size_t)n * 136 + m]           = __float2bfloat16(a[0] + bv0);
                Tb[(size_t)(n + 1) * 136 + m]     = __float2bfloat16(a[1] + bv0);
                Tb[(size_t)n * 136 + m + 8]       = __float2bfloat16(a[2] + bv1);
                Tb[(size_t)(n + 1) * 136 + m + 8] = __float2bfloat16(a[3] + bv1);
            }
        }
        __syncthreads();
        int n = t >> 1, c = t & 1;
        const uint4* src = (const uint4*)((const char*)Tb + n * 272 + c * 128);
        uint4* dst = (uint4*)((char*)(g_VT + ((size_t)(b * Nn + n0 + n)) * Cc + ytile * 128) + c * 128);
#pragma unroll
        for (int u = 0; u < 8; u++) dst[u] = src[u];
    } else {
        __nv_bfloat16* Qt = (__nv_bfloat16*)(sm + PJ_XS);            // [128][24]
        __nv_bfloat16* Kt = (__nv_bfloat16*)(sm + PJ_XS + 6144);     // [16][136]
        if (mg == 0) {
            {
                int d = lane >> 2;
                float b0 = bq[d], b1 = bq[d + 8];
#pragma unroll
                for (int nb = 0; nb < 8; nb++) {
                    int n = ng * 64 + nb * 8 + (lane & 3) * 2;
                    float* a = acc[0][nb];
                    Qt[(size_t)n * 24 + d]           = __float2bfloat16((a[0] + b0) * QSCALE);
                    Qt[(size_t)(n + 1) * 24 + d]     = __float2bfloat16((a[1] + b0) * QSCALE);
                    Qt[(size_t)n * 24 + d + 8]       = __float2bfloat16((a[2] + b1) * QSCALE);
                    Qt[(size_t)(n + 1) * 24 + d + 8] = __float2bfloat16((a[3] + b1) * QSCALE);
                }
            }
            {
                int d = lane >> 2;
                float b0 = bk[d], b1 = bk[d + 8];
#pragma unroll
                for (int nb = 0; nb < 8; nb++) {
                    int n = ng * 64 + nb * 8 + (lane & 3) * 2;
                    float* a = acc[1][nb];
                    Kt[(size_t)d * 136 + n]           = __float2bfloat16(a[0] + b0);
                    Kt[(size_t)d * 136 + n + 1]       = __float2bfloat16(a[1] + b0);
                    Kt[(size_t)(d + 8) * 136 + n]     = __float2bfloat16(a[2] + b1);
                    Kt[(size_t)(d + 8) * 136 + n + 1] = __float2bfloat16(a[3] + b1);
                }
            }
        }
        __syncthreads();
        {
            int n = t >> 1, c = t & 1;
            const uint4* src = (const uint4*)((const char*)Qt + n * 48 + c * 16);
            uint4* dst = (uint4*)((char*)(g_Qb + ((size_t)(b * Nn + n0 + n)) * Dd) + c * 16);
            dst[0] = src[0];
        }
        {
            int d = t >> 4, c = t & 15;
            const uint4* src = (const uint4*)((const char*)Kt + d * 272 + c * 16);
            uint4* dst = (uint4*)((char*)(g_Kb + ((size_t)(b * Dd + d)) * Nn + n0) + c * 16);
            dst[0] = src[0];
        }
    }
}

// ================= fused attention: split-role FA2, P via smem =================
// smem: VS 3x33792 | KS 3x2304 @101376 | QS 6144 @108288 | PS 18432 @114432 | RS 1024 @132864
#define AT_VS 0
#define AT_KS 101376
#define AT_QS 108288
#define AT_PS 114432
#define AT_RS 132864
#define AT_BYTES 133888

__global__ __launch_bounds__(512, 1) void attn_kernel()
{
    extern __shared__ __align__(16) char sm[];
    uint32_t smU = smem_u32(sm);
    int t = threadIdx.x, b = blockIdx.y, m0 = blockIdx.x * BM;
    int wid = t >> 5, lane = t & 31;
    int mg = wid >> 1, jg = wid & 1;    // QK role: m16 x j32 (disjoint)
    int mg2 = wid >> 2, eg = wid & 3;   // PV role: m32 x e64

    const char* vb = (const char*)(g_VT + (size_t)b * Nn * Cc);
    const char* kb = (const char*)(g_Kb + (size_t)b * Dd * Nn);
    const char* qb = (const char*)(g_Qb + ((size_t)b * Nn + m0) * Dd);

    int vj = t >> 3, vc = t & 7;
    int kd = t >> 3, kc = t & 7;

    // prologue: stages 0,1 (+Q)
#pragma unroll
    for (int st = 0; st < 2; st++) {
        int n0 = st * BN;
        uint32_t dst = smU + AT_VS + st * 33792 + vj * 528 + vc * 16;
        const char* src = vb + ((size_t)(n0 + vj)) * 512 + vc * 16;
#pragma unroll
        for (int u = 0; u < 4; u++) cp16(dst + u * 128, src + u * 128);
        if (t < 128) cp16(smU + AT_KS + st * 2304 + kd * 144 + kc * 16,
                          kb + (size_t)kd * (Nn * 2) + n0 * 2 + kc * 16);
        if (st == 0 && t < 256) {
            int m = t >> 1, c = t & 1;
            cp16(smU + AT_QS + m * 48 + c * 16, qb + m * 32 + c * 16);
        }
        CP_COMMIT;
    }

    float acc[2][8][4];
#pragma unroll
    for (int i = 0; i < 2; i++)
#pragma unroll
        for (int j = 0; j < 8; j++)
#pragma unroll
            for (int q = 0; q < 4; q++) acc[i][j][q] = 0.f;

    uint32_t qa[4];
    float rs0 = 0.f, rs1 = 0.f;

    // P store base (QK role): row mg*16 + lane>>2, col jg*32 + (lane&3)*2
    uint32_t ps_st = smU + AT_PS + (mg * 16 + (lane >> 2)) * 144 + (jg * 32 + (lane & 3) * 2) * 2;
    // P ldsm base (PV role)
    uint32_t ps_ld = smU + AT_PS +
        (uint32_t)(mg2 * 32 + (lane & 7) + ((lane >> 3) & 1) * 8) * 144 + (lane >> 4) * 16;

    int s3 = 0, sp = 2;
    for (int it = 0; it < NTILES; it++) {
        CP_WAIT1;
        __syncthreads();                 // stage s3 ready; prev PV done with P
        if (it == 0) {
            uint32_t qaddr = smU + AT_QS +
                (mg * 16 + (lane & 7) + ((lane >> 3) & 1) * 8) * 48 + (lane >> 4) * 16;
            ldsm_x4(qa[0], qa[1], qa[2], qa[3], qaddr);
        }
        uint32_t vsb = smU + AT_VS + s3 * 33792;
        uint32_t ksb = smU + AT_KS + s3 * 2304;

        // ---- QK phase: each warp m16 x j32, exp in log2 domain, P -> smem ----
#pragma unroll
        for (int nb2 = 0; nb2 < 2; nb2++) {
            float c[2][4];
#pragma unroll
            for (int h = 0; h < 2; h++)
#pragma unroll
                for (int j = 0; j < 4; j++) c[h][j] = 0.f;
            uint32_t b0, b1, b2, b3;
            uint32_t ka = ksb + (lane & 15) * 144 + (jg * 32 + nb2 * 16 + (lane >> 4) * 8) * 2;
            ldsm_x4t(b0, b1, b2, b3, ka);
            mma16816(c[0], qa, b0, b1);
            mma16816(c[1], qa, b2, b3);
#pragma unroll
            for (int h = 0; h < 2; h++) {
                float e0 = ex2(fminf(fmaxf(c[h][0], -CLIP2), CLIP2));
                float e1 = ex2(fminf(fmaxf(c[h][1], -CLIP2), CLIP2));
                float e2 = ex2(fminf(fmaxf(c[h][2], -CLIP2), CLIP2));
                float e3 = ex2(fminf(fmaxf(c[h][3], -CLIP2), CLIP2));
                rs0 += e0 + e1;
                rs1 += e2 + e3;
                __nv_bfloat162 lo = __floats2bfloat162_rn(e0, e1);
                __nv_bfloat162 hi = __floats2bfloat162_rn(e2, e3);
                sts32(ps_st + nb2 * 32 + h * 16, *(uint32_t*)&lo);
                sts32(ps_st + nb2 * 32 + h * 16 + 8 * 144, *(uint32_t*)&hi);
            }
        }
        __syncthreads();                 // P visible to all warps

        // prefetch it+2 into stage sp (disjoint from read stage; no barrier needed)
        if (it + 2 < NTILES) {
            int n0 = (it + 2) * BN;
            uint32_t dst = smU + AT_VS + sp * 33792 + vj * 528 + vc * 16;
            const char* src = vb + ((size_t)(n0 + vj)) * 512 + vc * 16;
#pragma unroll
            for (int u = 0; u < 4; u++) cp16(dst + u * 128, src + u * 128);
            if (t < 128) cp16(smU + AT_KS + sp * 2304 + kd * 144 + kc * 16,
                              kb + (size_t)kd * (Nn * 2) + n0 * 2 + kc * 16);
        }
        CP_COMMIT;

        // ---- PV phase: each warp m32 x e64 ----
#pragma unroll
        for (int kg = 0; kg < 4; kg++) {
            uint32_t pA[2][4];
#pragma unroll
            for (int mi = 0; mi < 2; mi++)
                ldsm_x4(pA[mi][0], pA[mi][1], pA[mi][2], pA[mi][3],
                        ps_ld + mi * (16 * 144) + kg * 32);
#pragma unroll
            for (int eb2 = 0; eb2 < 4; eb2++) {
                uint32_t b0, b1, b2, b3;
                uint32_t va = vsb + (kg * 16 + (lane & 15)) * 528 +
                              (eg * 64 + eb2 * 16 + (lane >> 4) * 8) * 2;
                ldsm_x4t(b0, b1, b2, b3, va);
                mma16816(acc[0][eb2 * 2],     pA[0], b0, b1);
                mma16816(acc[0][eb2 * 2 + 1], pA[0], b2, b3);
                mma16816(acc[1][eb2 * 2],     pA[1], b0, b1);
                mma16816(acc[1][eb2 * 2 + 1], pA[1], b2, b3);
            }
        }
        s3 = (s3 == 2) ? 0 : s3 + 1;
        sp = (sp == 2) ? 0 : sp + 1;
    }

    // rowsum: reduce over lane quad, combine jg halves via smem
    rs0 += __shfl_xor_sync(0xffffffffu, rs0, 1);
    rs0 += __shfl_xor_sync(0xffffffffu, rs0, 2);
    rs1 += __shfl_xor_sync(0xffffffffu, rs1, 1);
    rs1 += __shfl_xor_sync(0xffffffffu, rs1, 2);
    float* rs_s = (float*)(sm + AT_RS);
    if ((lane & 3) == 0) {
        rs_s[jg * 128 + mg * 16 + (lane >> 2)]     = rs0;
        rs_s[jg * 128 + mg * 16 + (lane >> 2) + 8] = rs1;
    }
    __syncthreads();

    int r = lane >> 2, q = lane & 3;
    float* ob = g_OA + (size_t)b * Cc * Nn;
#pragma unroll
    for (int mi = 0; mi < 2; mi++) {
        int ml = mg2 * 32 + mi * 16 + r;
        float inv0 = 1.f / (rs_s[ml]     + rs_s[128 + ml]);
        float inv1 = 1.f / (rs_s[ml + 8] + rs_s[128 + ml + 8]);
        int mrow = m0 + ml;
#pragma unroll
        for (int nb = 0; nb < 8; nb++) {
            int e = eg * 64 + nb * 8 + 2 * q;
            float* p0 = ob + (size_t)e * Nn;
            p0[mrow]          = acc[mi][nb][0] * inv0;
            p0[Nn + mrow]     = acc[mi][nb][1] * inv0;
            p0[mrow + 8]      = acc[mi][nb][2] * inv1;
            p0[Nn + mrow + 8] = acc[mi][nb][3] * inv1;
        }
    }
}

// ================= output projection via tf32 MMA + residual =================
__global__ __launch_bounds__(256, 2) void outproj_kernel(
    const float* __restrict__ x,
    const float* __restrict__ Wo, const float* __restrict__ bo,
    const float* __restrict__ gamma, float* __restrict__ out)
{
    extern __shared__ __align__(16) char sm[];
    uint32_t smU = smem_u32(sm);
    int t = threadIdx.x, wid = t >> 5, lane = t & 31;
    int mg = wid >> 1, ng = wid & 1;
    int n0 = blockIdx.x * 128, ytile = blockIdx.y, b = blockIdx.z;

    int wm = t >> 1, wq4 = t & 1;
    const float* wsrc = Wo + (ytile * 128 + wm) * Cc;
    const float* xb = g_OA + (size_t)b * Cc * Nn + n0;
    int xk = t >> 3, xn = t & 7;

#pragma unroll
    for (int ch = 0; ch < 2; ch++) {
        int k0 = ch * 32, st = ch & 1;
#pragma unroll
        for (int u = 0; u < 4; u++) {
            int kq = wq4 + 2 * u;
            cp16(smU + PJ_WS + st * 18432 + wm * 144 + kq * 16, wsrc + k0 + kq * 4);
        }
#pragma unroll
        for (int u = 0; u < 4; u++) {
            int nq = xn + 8 * u;
            cp16(smU + PJ_XS + st * 17408 + xk * 544 + nq * 16, xb + (size_t)(k0 + xk) * Nn + nq * 4);
        }
        CP_COMMIT;
    }

    float acc[2][8][4];
#pragma unroll
    for (int i = 0; i < 2; i++)
#pragma unroll
        for (int j = 0; j < 8; j++)
#pragma unroll
            for (int q = 0; q < 4; q++) acc[i][j][q] = 0.f;

    for (int ch = 0; ch < 8; ch++) {
        int st = ch & 1;
        CP_WAIT1;
        __syncthreads();
        {
            const float* wb = (const float*)(sm + PJ_WS + st * 18432);
            const float* xs = (const float*)(sm + PJ_XS + st * 17408);
#pragma unroll
            for (int k8 = 0; k8 < 4; k8++) {
                uint32_t A[2][4];
#pragma unroll
                for (int mi = 0; mi < 2; mi++) {
                    const float* ap = wb + (mg * 32 + mi * 16 + (lane >> 2)) * 36 + k8 * 8 + (lane & 3);
                    A[mi][0] = cvt_tf32(ap[0]);
                    A[mi][2] = cvt_tf32(ap[4]);
                    A[mi][1] = cvt_tf32(ap[8 * 36]);
                    A[mi][3] = cvt_tf32(ap[8 * 36 + 4]);
                }
                const float* bp = xs + (k8 * 8 + (lane & 3)) * 136 + ng * 64 + (lane >> 2);
#pragma unroll
                for (int nb = 0; nb < 8; nb++) {
                    uint32_t b0 = cvt_tf32(bp[nb * 8]);
                    uint32_t b1 = cvt_tf32(bp[nb * 8 + 4 * 136]);
                    mma_tf32(acc[0][nb], A[0], b0, b1);
                    mma_tf32(acc[1][nb], A[1], b0, b1);
                }
            }
        }
        __syncthreads();
        if (ch + 2 < 8) {
            int k0 = (ch + 2) * 32;
#pragma unroll
            for (int u = 0; u < 4; u++) {
                int kq = wq4 + 2 * u;
                cp16(smU + PJ_WS + st * 18432 + wm * 144 + kq * 16, wsrc + k0 + kq * 4);
            }
#pragma unroll
            for (int u = 0; u < 4; u++) {
                int nq = xn + 8 * u;
                cp16(smU + PJ_XS + st * 17408 + xk * 544 + nq * 16, xb + (size_t)(k0 + xk) * Nn + nq * 4);
            }
        }
        CP_COMMIT;
    }
    __syncthreads();

    float* Tf = (float*)sm;
#pragma unroll
    for (int mi = 0; mi < 2; mi++) {
        int m = mg * 32 + mi * 16 + (lane >> 2);
#pragma unroll
        for (int nb = 0; nb < 8; nb++) {
            int n = ng * 64 + nb * 8 + (lane & 3) * 2;
            float* a = acc[mi][nb];
            *(float2*)(Tf + (size_t)m * 132 + n)       = make_float2(a[0], a[1]);
            *(float2*)(Tf + (size_t)(m + 8) * 132 + n) = make_float2(a[2], a[3]);
        }
    }
    __syncthreads();
    float g = fminf(fmaxf(gamma[0], 0.f), 1.f);
    {
        int m = t >> 1, c = t & 1;
        int mglob = ytile * 128 + m;
        float bb = bo[mglob];
        size_t base = ((size_t)(b * Cc + mglob)) * Nn + n0 + c * 64;
#pragma unroll
        for (int u = 0; u < 16; u++) {
            float4 v = *(const float4*)(Tf + (size_t)m * 132 + c * 64 + u * 4);
            float4 xr = *(const float4*)(x + base + u * 4);
            float4 o;
            o.x = g * (v.x + bb) + xr.x;
            o.y = g * (v.y + bb) + xr.y;
            o.z = g * (v.z + bb) + xr.z;
            o.w = g * (v.w + bb) + xr.w;
            *(float4*)(out + base + u * 4) = o;
        }
    }
}

// ---------------- launcher ----------------
extern "C" void kernel_launch(void* const* d_in, const int* in_sizes, int n_in,
                              void* d_out, int out_size)
{
    const float* x     = (const float*)d_in[0];
    const float* Wq    = (const float*)d_in[1];
    const float* bq    = (const float*)d_in[2];
    const float* Wk    = (const float*)d_in[3];
    const float* bk    = (const float*)d_in[4];
    const float* Wv    = (const float*)d_in[5];
    const float* bv    = (const float*)d_in[6];
    const float* Wo    = (const float*)d_in[7];
    const float* bo    = (const float*)d_in[8];
    const float* gamma = (const float*)d_in[9];
    float* out = (float*)d_out;

    cudaFuncSetAttribute(proj_kernel,    cudaFuncAttributeMaxDynamicSharedMemorySize, PJ_BYTES);
    cudaFuncSetAttribute(outproj_kernel, cudaFuncAttributeMaxDynamicSharedMemorySize, PJ_BYTES);
    cudaFuncSetAttribute(attn_kernel,    cudaFuncAttributeMaxDynamicSharedMemorySize, AT_BYTES);

    proj_kernel   <<<dim3(Nn / 128, 3, Bb), 256, PJ_BYTES>>>(x, Wq, bq, Wk, bk, Wv, bv);
    attn_kernel   <<<dim3(Nn / BM, Bb), 512, AT_BYTES>>>();
    outproj_kernel<<<dim3(Nn / 128, 2, Bb), 256, PJ_BYTES>>>(x, Wo, bo, gamma, out);
}

// round 9
// speedup vs baseline: 6.9020x; 1.0044x over previous
#include <cuda_runtime.h>
#include <cuda_bf16.h>
#include <cstdint>

#define Bb 8
#define Cc 256
#define Nn 4096
#define Dd 16
#define BM 128
#define BN 64
#define NTILES (Nn / BN)

typedef unsigned long long ull;

// ---------------- scratch ----------------
__device__ __nv_bfloat16 g_Qb[(size_t)Bb * Nn * Dd];   // [B,N,16] bf16, (q+bq)*0.25*log2e
__device__ __nv_bfloat16 g_Kb[(size_t)Bb * Dd * Nn];   // [B,16,N] bf16, k+bk
__device__ __nv_bfloat16 g_VT[(size_t)Bb * Nn * Cc];   // [B,N,C] bf16
__device__ float g_OA[(size_t)Bb * Cc * Nn];           // [B,C,N]

// ---------------- helpers ----------------
static __device__ __forceinline__ uint32_t smem_u32(const void* p) {
    uint32_t a;
    asm("{ .reg .u64 t; cvta.to.shared.u64 t, %1; cvt.u32.u64 %0, t; }" : "=r"(a) : "l"(p));
    return a;
}
static __device__ __forceinline__ void ldsm_x4(uint32_t &r0, uint32_t &r1, uint32_t &r2, uint32_t &r3, uint32_t addr) {
    asm volatile("ldmatrix.sync.aligned.m8n8.x4.shared.b16 {%0,%1,%2,%3}, [%4];"
                 : "=r"(r0), "=r"(r1), "=r"(r2), "=r"(r3) : "r"(addr));
}
static __device__ __forceinline__ void ldsm_x4t(uint32_t &r0, uint32_t &r1, uint32_t &r2, uint32_t &r3, uint32_t addr) {
    asm volatile("ldmatrix.sync.aligned.m8n8.x4.trans.shared.b16 {%0,%1,%2,%3}, [%4];"
                 : "=r"(r0), "=r"(r1), "=r"(r2), "=r"(r3) : "r"(addr));
}
static __device__ __forceinline__ void mma16816(float* d, const uint32_t* a, uint32_t b0, uint32_t b1) {
    asm volatile("mma.sync.aligned.m16n8k16.row.col.f32.bf16.bf16.f32 "
                 "{%0,%1,%2,%3}, {%4,%5,%6,%7}, {%8,%9}, {%0,%1,%2,%3};"
                 : "+f"(d[0]), "+f"(d[1]), "+f"(d[2]), "+f"(d[3])
                 : "r"(a[0]), "r"(a[1]), "r"(a[2]), "r"(a[3]), "r"(b0), "r"(b1));
}
static __device__ __forceinline__ void mma_tf32(float* d, const uint32_t* a, uint32_t b0, uint32_t b1) {
    asm volatile("mma.sync.aligned.m16n8k8.row.col.f32.tf32.tf32.f32 "
                 "{%0,%1,%2,%3}, {%4,%5,%6,%7}, {%8,%9}, {%0,%1,%2,%3};"
                 : "+f"(d[0]), "+f"(d[1]), "+f"(d[2]), "+f"(d[3])
                 : "r"(a[0]), "r"(a[1]), "r"(a[2]), "r"(a[3]), "r"(b0), "r"(b1));
}
static __device__ __forceinline__ float ex2(float x) {
    float y; asm("ex2.approx.ftz.f32 %0, %1;" : "=f"(y) : "f"(x)); return y;
}
static __device__ __forceinline__ void sts32(uint32_t addr, uint32_t v) {
    asm volatile("st.shared.b32 [%0], %1;" :: "r"(addr), "r"(v));
}
static __device__ __forceinline__ void cp16(uint32_t dst, const void* src) {
    asm volatile("cp.async.cg.shared.global [%0], [%1], 16;" :: "r"(dst), "l"(src));
}
#define CP_COMMIT asm volatile("cp.async.commit_group;" ::: "memory")
#define CP_WAIT1  asm volatile("cp.async.wait_group 1;" ::: "memory")

#define QSCALE 0.36067376022224085f   // 0.25 * log2(e)
#define CLIP2  72.134752f             // 50 * log2(e)

// ================= fused projection: V (+Q,K) via tf32 MMA (raw-bit RZ) =================
#define PJ_WS 0
#define PJ_XS 36864
#define PJ_BYTES (36864 + 34816)

__global__ __launch_bounds__(256, 2) void proj_kernel(
    const float* __restrict__ x,
    const float* __restrict__ Wq, const float* __restrict__ bq,
    const float* __restrict__ Wk, const float* __restrict__ bk,
    const float* __restrict__ Wv, const float* __restrict__ bv)
{
    extern __shared__ __align__(16) char sm[];
    uint32_t smU = smem_u32(sm);
    int t = threadIdx.x, wid = t >> 5, lane = t & 31;
    int mg = wid >> 1, ng = wid & 1;
    int n0 = blockIdx.x * 128, ytile = blockIdx.y, b = blockIdx.z;
    bool active = (ytile < 2) || (mg == 0);

    int wm = t >> 1, wq4 = t & 1;
    const float* wsrc;
    bool wvalid = true;
    if (ytile < 2) wsrc = Wv + (ytile * 128 + wm) * Cc;
    else {
        if (wm < 16) wsrc = Wq + wm * Cc;
        else if (wm < 32) wsrc = Wk + (wm - 16) * Cc;
        else { wsrc = Wq; wvalid = false; }
    }
    const float* xb = x + (size_t)b * Cc * Nn + n0;
    int xk = t >> 3, xn = t & 7;

#pragma unroll
    for (int ch = 0; ch < 2; ch++) {
        int k0 = ch * 32, st = ch & 1;
        if (wvalid) {
#pragma unroll
            for (int u = 0; u < 4; u++) {
                int kq = wq4 + 2 * u;
                cp16(smU + PJ_WS + st * 18432 + wm * 144 + kq * 16, wsrc + k0 + kq * 4);
            }
        }
#pragma unroll
        for (int u = 0; u < 4; u++) {
            int nq = xn + 8 * u;
            cp16(smU + PJ_XS + st * 17408 + xk * 544 + nq * 16, xb + (size_t)(k0 + xk) * Nn + nq * 4);
        }
        CP_COMMIT;
    }

    float acc[2][8][4];
#pragma unroll
    for (int i = 0; i < 2; i++)
#pragma unroll
        for (int j = 0; j < 8; j++)
#pragma unroll
            for (int q = 0; q < 4; q++) acc[i][j][q] = 0.f;

    for (int ch = 0; ch < 8; ch++) {
        int st = ch & 1;
        CP_WAIT1;
        __syncthreads();
        if (active) {
            const float* wb = (const float*)(sm + PJ_WS + st * 18432);
            const float* xs = (const float*)(sm + PJ_XS + st * 17408);
#pragma unroll
            for (int k8 = 0; k8 < 4; k8++) {
                uint32_t A[2][4];
#pragma unroll
                for (int mi = 0; mi < 2; mi++) {
                    const float* ap = wb + (mg * 32 + mi * 16 + (lane >> 2)) * 36 + k8 * 8 + (lane & 3);
                    A[mi][0] = __float_as_uint(ap[0]);
                    A[mi][2] = __float_as_uint(ap[4]);
                    A[mi][1] = __float_as_uint(ap[8 * 36]);
                    A[mi][3] = __float_as_uint(ap[8 * 36 + 4]);
                }
                const float* bp = xs + (k8 * 8 + (lane & 3)) * 136 + ng * 64 + (lane >> 2);
#pragma unroll
                for (int nb = 0; nb < 8; nb++) {
                    uint32_t b0 = __float_as_uint(bp[nb * 8]);
                    uint32_t b1 = __float_as_uint(bp[nb * 8 + 4 * 136]);
                    mma_tf32(acc[0][nb], A[0], b0, b1);
                    mma_tf32(acc[1][nb], A[1], b0, b1);
                }
            }
        }
        __syncthreads();
        if (ch + 2 < 8) {
            int k0 = (ch + 2) * 32;
            if (wvalid) {
#pragma unroll
                for (int u = 0; u < 4; u++) {
                    int kq = wq4 + 2 * u;
                    cp16(smU + PJ_WS + st * 18432 + wm * 144 + kq * 16, wsrc + k0 + kq * 4);
                }
            }
#pragma unroll
            for (int u = 0; u < 4; u++) {
                int nq = xn + 8 * u;
                cp16(smU + PJ_XS + st * 17408 + xk * 544 + nq * 16, xb + (size_t)(k0 + xk) * Nn + nq * 4);
            }
        }
        CP_COMMIT;
    }
    __syncthreads();

    if (ytile < 2) {
        __nv_bfloat16* Tb = (__nv_bfloat16*)(sm + PJ_XS);
#pragma unroll
        for (int mi = 0; mi < 2; mi++) {
            int m = mg * 32 + mi * 16 + (lane >> 2);
            float bv0 = bv[ytile * 128 + m];
            float bv1 = bv[ytile * 128 + m + 8];
#pragma unroll
            for (int nb = 0; nb < 8; nb++) {
                int n = ng * 64 + nb * 8 + (lane & 3) * 2;
                float* a = acc[mi][nb];
                Tb[(size_t)n * 136 + m]           = __float2bfloat16(a[0] + bv0);
                Tb[(size_t)(n + 1) * 136 + m]     = __float2bfloat16(a[1] + bv0);
                Tb[(size_t)n * 136 + m + 8]       = __float2bfloat16(a[2] + bv1);
                Tb[(size_t)(n + 1) * 136 + m + 8] = __float2bfloat16(a[3] + bv1);
            }
        }
        __syncthreads();
        int n = t >> 1, c = t & 1;
        const uint4* src = (const uint4*)((const char*)Tb + n * 272 + c * 128);
        uint4* dst = (uint4*)((char*)(g_VT + ((size_t)(b * Nn + n0 + n)) * Cc + ytile * 128) + c * 128);
#pragma unroll
        for (int u = 0; u < 8; u++) dst[u] = src[u];
    } else {
        __nv_bfloat16* Qt = (__nv_bfloat16*)(sm + PJ_XS);            // [128][24]
        __nv_bfloat16* Kt = (__nv_bfloat16*)(sm + PJ_XS + 6144);     // [16][136]
        if (mg == 0) {
            {
                int d = lane >> 2;
                float b0 = bq[d], b1 = bq[d + 8];
#pragma unroll
                for (int nb = 0; nb < 8; nb++) {
                    int n = ng * 64 + nb * 8 + (lane & 3) * 2;
                    float* a = acc[0][nb];
                    Qt[(size_t)n * 24 + d]           = __float2bfloat16((a[0] + b0) * QSCALE);
                    Qt[(size_t)(n + 1) * 24 + d]     = __float2bfloat16((a[1] + b0) * QSCALE);
                    Qt[(size_t)n * 24 + d + 8]       = __float2bfloat16((a[2] + b1) * QSCALE);
                    Qt[(size_t)(n + 1) * 24 + d + 8] = __float2bfloat16((a[3] + b1) * QSCALE);
                }
            }
            {
                int d = lane >> 2;
                float b0 = bk[d], b1 = bk[d + 8];
#pragma unroll
                for (int nb = 0; nb < 8; nb++) {
                    int n = ng * 64 + nb * 8 + (lane & 3) * 2;
                    float* a = acc[1][nb];
                    Kt[(size_t)d * 136 + n]           = __float2bfloat16(a[0] + b0);
                    Kt[(size_t)d * 136 + n + 1]       = __float2bfloat16(a[1] + b0);
                    Kt[(size_t)(d + 8) * 136 + n]     = __float2bfloat16(a[2] + b1);
                    Kt[(size_t)(d + 8) * 136 + n + 1] = __float2bfloat16(a[3] + b1);
                }
            }
        }
        __syncthreads();
        {
            int n = t >> 1, c = t & 1;
            const uint4* src = (const uint4*)((const char*)Qt + n * 48 + c * 16);
            uint4* dst = (uint4*)((char*)(g_Qb + ((size_t)(b * Nn + n0 + n)) * Dd) + c * 16);
            dst[0] = src[0];
        }
        {
            int d = t >> 4, c = t & 15;
            const uint4* src = (const uint4*)((const char*)Kt + d * 272 + c * 16);
            uint4* dst = (uint4*)((char*)(g_Kb + ((size_t)(b * Dd + d)) * Nn + n0) + c * 16);
            dst[0] = src[0];
        }
    }
}

// ================= fused attention: split-role FA2, P via smem =================
// smem: VS 3x33792 | KS 3x2304 @101376 | QS 6144 @108288 | PS 18432 @114432 | RS 1024 @132864
#define AT_VS 0
#define AT_KS 101376
#define AT_QS 108288
#define AT_PS 114432
#define AT_RS 132864
#define AT_BYTES 133888

__global__ __launch_bounds__(512, 1) void attn_kernel()
{
    extern __shared__ __align__(16) char sm[];
    uint32_t smU = smem_u32(sm);
    int t = threadIdx.x, b = blockIdx.y, m0 = blockIdx.x * BM;
    int wid = t >> 5, lane = t & 31;
    int mg = wid >> 1, jg = wid & 1;    // QK role: m16 x j32 (disjoint)
    int mg2 = wid >> 2, eg = wid & 3;   // PV role: m32 x e64

    const char* vb = (const char*)(g_VT + (size_t)b * Nn * Cc);
    const char* kb = (const char*)(g_Kb + (size_t)b * Dd * Nn);
    const char* qb = (const char*)(g_Qb + ((size_t)b * Nn + m0) * Dd);

    int vj = t >> 3, vc = t & 7;
    int kd = t >> 3, kc = t & 7;

    // prologue: stages 0,1 (+Q)
#pragma unroll
    for (int st = 0; st < 2; st++) {
        int n0 = st * BN;
        uint32_t dst = smU + AT_VS + st * 33792 + vj * 528 + vc * 16;
        const char* src = vb + ((size_t)(n0 + vj)) * 512 + vc * 16;
#pragma unroll
        for (int u = 0; u < 4; u++) cp16(dst + u * 128, src + u * 128);
        if (t < 128) cp16(smU + AT_KS + st * 2304 + kd * 144 + kc * 16,
                          kb + (size_t)kd * (Nn * 2) + n0 * 2 + kc * 16);
        if (st == 0 && t < 256) {
            int m = t >> 1, c = t & 1;
            cp16(smU + AT_QS + m * 48 + c * 16, qb + m * 32 + c * 16);
        }
        CP_COMMIT;
    }

    float acc[2][8][4];
#pragma unroll
    for (int i = 0; i < 2; i++)
#pragma unroll
        for (int j = 0; j < 8; j++)
#pragma unroll
            for (int q = 0; q < 4; q++) acc[i][j][q] = 0.f;

    uint32_t qa[4];
    float rs0 = 0.f, rs1 = 0.f;

    uint32_t ps_st = smU + AT_PS + (mg * 16 + (lane >> 2)) * 144 + (jg * 32 + (lane & 3) * 2) * 2;
    uint32_t ps_ld = smU + AT_PS +
        (uint32_t)(mg2 * 32 + (lane & 7) + ((lane >> 3) & 1) * 8) * 144 + (lane >> 4) * 16;

    int s3 = 0, sp = 2;
    for (int it = 0; it < NTILES; it++) {
        CP_WAIT1;
        __syncthreads();
        if (it == 0) {
            uint32_t qaddr = smU + AT_QS +
                (mg * 16 + (lane & 7) + ((lane >> 3) & 1) * 8) * 48 + (lane >> 4) * 16;
            ldsm_x4(qa[0], qa[1], qa[2], qa[3], qaddr);
        }
        uint32_t vsb = smU + AT_VS + s3 * 33792;
        uint32_t ksb = smU + AT_KS + s3 * 2304;

        // ---- QK phase ----
#pragma unroll
        for (int nb2 = 0; nb2 < 2; nb2++) {
            float c[2][4];
#pragma unroll
            for (int h = 0; h < 2; h++)
#pragma unroll
                for (int j = 0; j < 4; j++) c[h][j] = 0.f;
            uint32_t b0, b1, b2, b3;
            uint32_t ka = ksb + (lane & 15) * 144 + (jg * 32 + nb2 * 16 + (lane >> 4) * 8) * 2;
            ldsm_x4t(b0, b1, b2, b3, ka);
            mma16816(c[0], qa, b0, b1);
            mma16816(c[1], qa, b2, b3);
#pragma unroll
            for (int h = 0; h < 2; h++) {
                float e0 = ex2(fminf(fmaxf(c[h][0], -CLIP2), CLIP2));
                float e1 = ex2(fminf(fmaxf(c[h][1], -CLIP2), CLIP2));
                float e2 = ex2(fminf(fmaxf(c[h][2], -CLIP2), CLIP2));
                float e3 = ex2(fminf(fmaxf(c[h][3], -CLIP2), CLIP2));
                rs0 += e0 + e1;
                rs1 += e2 + e3;
                __nv_bfloat162 lo = __floats2bfloat162_rn(e0, e1);
                __nv_bfloat162 hi = __floats2bfloat162_rn(e2, e3);
                sts32(ps_st + nb2 * 32 + h * 16, *(uint32_t*)&lo);
                sts32(ps_st + nb2 * 32 + h * 16 + 8 * 144, *(uint32_t*)&hi);
            }
        }
        __syncthreads();

        if (it + 2 < NTILES) {
            int n0 = (it + 2) * BN;
            uint32_t dst = smU + AT_VS + sp * 33792 + vj * 528 + vc * 16;
            const char* src = vb + ((size_t)(n0 + vj)) * 512 + vc * 16;
#pragma unroll
            for (int u = 0; u < 4; u++) cp16(dst + u * 128, src + u * 128);
            if (t < 128) cp16(smU + AT_KS + sp * 2304 + kd * 144 + kc * 16,
                              kb + (size_t)kd * (Nn * 2) + n0 * 2 + kc * 16);
        }
        CP_COMMIT;

        // ---- PV phase ----
#pragma unroll
        for (int kg = 0; kg < 4; kg++) {
            uint32_t pA[2][4];
#pragma unroll
            for (int mi = 0; mi < 2; mi++)
                ldsm_x4(pA[mi][0], pA[mi][1], pA[mi][2], pA[mi][3],
                        ps_ld + mi * (16 * 144) + kg * 32);
#pragma unroll
            for (int eb2 = 0; eb2 < 4; eb2++) {
                uint32_t b0, b1, b2, b3;
                uint32_t va = vsb + (kg * 16 + (lane & 15)) * 528 +
                              (eg * 64 + eb2 * 16 + (lane >> 4) * 8) * 2;
                ldsm_x4t(b0, b1, b2, b3, va);
                mma16816(acc[0][eb2 * 2],     pA[0], b0, b1);
                mma16816(acc[0][eb2 * 2 + 1], pA[0], b2, b3);
                mma16816(acc[1][eb2 * 2],     pA[1], b0, b1);
                mma16816(acc[1][eb2 * 2 + 1], pA[1], b2, b3);
            }
        }
        s3 = (s3 == 2) ? 0 : s3 + 1;
        sp = (sp == 2) ? 0 : sp + 1;
    }

    // rowsum reduce + stash
    rs0 += __shfl_xor_sync(0xffffffffu, rs0, 1);
    rs0 += __shfl_xor_sync(0xffffffffu, rs0, 2);
    rs1 += __shfl_xor_sync(0xffffffffu, rs1, 1);
    rs1 += __shfl_xor_sync(0xffffffffu, rs1, 2);
    float* rs_s = (float*)(sm + AT_RS);
    if ((lane & 3) == 0) {
        rs_s[jg * 128 + mg * 16 + (lane >> 2)]     = rs0;
        rs_s[jg * 128 + mg * 16 + (lane >> 2) + 8] = rs1;
    }

    // epilogue: normalize -> smem stage [e128 x 132] -> coalesced stores (2 e-halves)
    float* Tf = (float*)sm;
    float* ob = g_OA + (size_t)b * Cc * Nn + m0;
    int r = lane >> 2, q = lane & 3;
#pragma unroll
    for (int h = 0; h < 2; h++) {
        __syncthreads();   // h=0: PV readers done + rs_s visible; h=1: pass-0 copies done
        if ((eg >> 1) == h) {
            int ebase = (eg & 1) * 64;
#pragma unroll
            for (int mi = 0; mi < 2; mi++) {
                int ml = mg2 * 32 + mi * 16 + r;
                float inv0 = 1.f / (rs_s[ml]     + rs_s[128 + ml]);
                float inv1 = 1.f / (rs_s[ml + 8] + rs_s[128 + ml + 8]);
#pragma unroll
                for (int nb = 0; nb < 8; nb++) {
                    int e = ebase + nb * 8 + 2 * q;
                    float* a = acc[mi][nb];
                    Tf[(size_t)e * 132 + ml]           = a[0] * inv0;
                    Tf[(size_t)(e + 1) * 132 + ml]     = a[1] * inv0;
                    Tf[(size_t)e * 132 + ml + 8]       = a[2] * inv1;
                    Tf[(size_t)(e + 1) * 132 + ml + 8] = a[3] * inv1;
                }
            }
        }
        __syncthreads();
        // copy out: warp wid -> rows wid*8..+7, each row 128 floats, fully coalesced
#pragma unroll
        for (int rr = 0; rr < 8; rr++) {
            int e = wid * 8 + rr;
            const float* srcr = Tf + (size_t)e * 132;
            float* dstr = ob + (size_t)(h * 128 + e) * Nn;
#pragma unroll
            for (int c = 0; c < 4; c++)
                dstr[c * 32 + lane] = srcr[c * 32 + lane];
        }
    }
}

// ================= output projection via tf32 MMA (raw-bit RZ) + residual =================
__global__ __launch_bounds__(256, 2) void outproj_kernel(
    const float* __restrict__ x,
    const float* __restrict__ Wo, const float* __restrict__ bo,
    const float* __restrict__ gamma, float* __restrict__ out)
{
    extern __shared__ __align__(16) char sm[];
    uint32_t smU = smem_u32(sm);
    int t = threadIdx.x, wid = t >> 5, lane = t & 31;
    int mg = wid >> 1, ng = wid & 1;
    int n0 = blockIdx.x * 128, ytile = blockIdx.y, b = blockIdx.z;

    int wm = t >> 1, wq4 = t & 1;
    const float* wsrc = Wo + (ytile * 128 + wm) * Cc;
    const float* xb = g_OA + (size_t)b * Cc * Nn + n0;
    int xk = t >> 3, xn = t & 7;

#pragma unroll
    for (int ch = 0; ch < 2; ch++) {
        int k0 = ch * 32, st = ch & 1;
#pragma unroll
        for (int u = 0; u < 4; u++) {
            int kq = wq4 + 2 * u;
            cp16(smU + PJ_WS + st * 18432 + wm * 144 + kq * 16, wsrc + k0 + kq * 4);
        }
#pragma unroll
        for (int u = 0; u < 4; u++) {
            int nq = xn + 8 * u;
            cp16(smU + PJ_XS + st * 17408 + xk * 544 + nq * 16, xb + (size_t)(k0 + xk) * Nn + nq * 4);
        }
        CP_COMMIT;
    }

    float acc[2][8][4];
#pragma unroll
    for (int i = 0; i < 2; i++)
#pragma unroll
        for (int j = 0; j < 8; j++)
#pragma unroll
            for (int q = 0; q < 4; q++) acc[i][j][q] = 0.f;

    for (int ch = 0; ch < 8; ch++) {
        int st = ch & 1;
        CP_WAIT1;
        __syncthreads();
        {
            const float* wb = (const float*)(sm + PJ_WS + st * 18432);
            const float* xs = (const float*)(sm + PJ_XS + st * 17408);
#pragma unroll
            for (int k8 = 0; k8 < 4; k8++) {
                uint32_t A[2][4];
#pragma unroll
                for (int mi = 0; mi < 2; mi++) {
                    const float* ap = wb + (mg * 32 + mi * 16 + (lane >> 2)) * 36 + k8 * 8 + (lane & 3);
                    A[mi][0] = __float_as_uint(ap[0]);
                    A[mi][2] = __float_as_uint(ap[4]);
                    A[mi][1] = __float_as_uint(ap[8 * 36]);
                    A[mi][3] = __float_as_uint(ap[8 * 36 + 4]);
                }
                const float* bp = xs + (k8 * 8 + (lane & 3)) * 136 + ng * 64 + (lane >> 2);
#pragma unroll
                for (int nb = 0; nb < 8; nb++) {
                    uint32_t b0 = __float_as_uint(bp[nb * 8]);
                    uint32_t b1 = __float_as_uint(bp[nb * 8 + 4 * 136]);
                    mma_tf32(acc[0][nb], A[0], b0, b1);
                    mma_tf32(acc[1][nb], A[1], b0, b1);
                }
            }
        }
        __syncthreads();
        if (ch + 2 < 8) {
            int k0 = (ch + 2) * 32;
#pragma unroll
            for (int u = 0; u < 4; u++) {
                int kq = wq4 + 2 * u;
                cp16(smU + PJ_WS + st * 18432 + wm * 144 + kq * 16, wsrc + k0 + kq * 4);
            }
#pragma unroll
            for (int u = 0; u < 4; u++) {
                int nq = xn + 8 * u;
                cp16(smU + PJ_XS + st * 17408 + xk * 544 + nq * 16, xb + (size_t)(k0 + xk) * Nn + nq * 4);
            }
        }
        CP_COMMIT;
    }
    __syncthreads();

    float* Tf = (float*)sm;
#pragma unroll
    for (int mi = 0; mi < 2; mi++) {
        int m = mg * 32 + mi * 16 + (lane >> 2);
#pragma unroll
        for (int nb = 0; nb < 8; nb++) {
            int n = ng * 64 + nb * 8 + (lane & 3) * 2;
            float* a = acc[mi][nb];
            *(float2*)(Tf + (size_t)m * 132 + n)       = make_float2(a[0], a[1]);
            *(float2*)(Tf + (size_t)(m + 8) * 132 + n) = make_float2(a[2], a[3]);
        }
    }
    __syncthreads();
    float g = fminf(fmaxf(gamma[0], 0.f), 1.f);
    {
        int m = t >> 1, c = t & 1;
        int mglob = ytile * 128 + m;
        float bb = bo[mglob];
        size_t base = ((size_t)(b * Cc + mglob)) * Nn + n0 + c * 64;
#pragma unroll
        for (int u = 0; u < 16; u++) {
            float4 v = *(const float4*)(Tf + (size_t)m * 132 + c * 64 + u * 4);
            float4 xr = *(const float4*)(x + base + u * 4);
            float4 o;
            o.x = g * (v.x + bb) + xr.x;
            o.y = g * (v.y + bb) + xr.y;
            o.z = g * (v.z + bb) + xr.z;
            o.w = g * (v.w + bb) + xr.w;
            *(float4*)(out + base + u * 4) = o;
        }
    }
}

// ---------------- launcher ----------------
extern "C" void kernel_launch(void* const* d_in, const int* in_sizes, int n_in,
                              void* d_out, int out_size)
{
    const float* x     = (const float*)d_in[0];
    const float* Wq    = (const float*)d_in[1];
    const float* bq    = (const float*)d_in[2];
    const float* Wk    = (const float*)d_in[3];
    const float* bk    = (const float*)d_in[4];
    const float* Wv    = (const float*)d_in[5];
    const float* bv    = (const float*)d_in[6];
    const float* Wo    = (const float*)d_in[7];
    const float* bo    = (const float*)d_in[8];
    const float* gamma = (const float*)d_in[9];
    float* out = (float*)d_out;

    cudaFuncSetAttribute(proj_kernel,    cudaFuncAttributeMaxDynamicSharedMemorySize, PJ_BYTES);
    cudaFuncSetAttribute(outproj_kernel, cudaFuncAttributeMaxDynamicSharedMemorySize, PJ_BYTES);
    cudaFuncSetAttribute(attn_kernel,    cudaFuncAttributeMaxDynamicSharedMemorySize, AT_BYTES);

    proj_kernel   <<<dim3(Nn / 128, 3, Bb), 256, PJ_BYTES>>>(x, Wq, bq, Wk, bk, Wv, bv);
    attn_kernel   <<<dim3(Nn / BM, Bb), 512, AT_BYTES>>>();
    outproj_kernel<<<dim3(Nn / 128, 2, Bb), 256, PJ_BYTES>>>(x, Wo, bo, gamma, out);
}

// round 10
// speedup vs baseline: 7.2527x; 1.0508x over previous
#include <cuda_runtime.h>
#include <cuda_bf16.h>
#include <cstdint>

#define Bb 8
#define Cc 256
#define Nn 4096
#define Dd 16
#define BM 128
#define BN 64
#define NTILES (Nn / BN)

typedef unsigned long long ull;

// ---------------- scratch ----------------
__device__ __nv_bfloat16 g_Qb[(size_t)Bb * Nn * Dd];   // [B,N,16] bf16, (q+bq)*0.25*log2e
__device__ __nv_bfloat16 g_Kb[(size_t)Bb * Dd * Nn];   // [B,16,N] bf16, k+bk
__device__ __nv_bfloat16 g_VT[(size_t)Bb * Nn * Cc];   // [B,N,C] bf16
__device__ float g_OA[(size_t)Bb * Cc * Nn];           // [B,C,N]

// ---------------- helpers ----------------
static __device__ __forceinline__ uint32_t smem_u32(const void* p) {
    uint32_t a;
    asm("{ .reg .u64 t; cvta.to.shared.u64 t, %1; cvt.u32.u64 %0, t; }" : "=r"(a) : "l"(p));
    return a;
}
static __device__ __forceinline__ void ldsm_x4(uint32_t &r0, uint32_t &r1, uint32_t &r2, uint32_t &r3, uint32_t addr) {
    asm volatile("ldmatrix.sync.aligned.m8n8.x4.shared.b16 {%0,%1,%2,%3}, [%4];"
                 : "=r"(r0), "=r"(r1), "=r"(r2), "=r"(r3) : "r"(addr));
}
static __device__ __forceinline__ void ldsm_x4t(uint32_t &r0, uint32_t &r1, uint32_t &r2, uint32_t &r3, uint32_t addr) {
    asm volatile("ldmatrix.sync.aligned.m8n8.x4.trans.shared.b16 {%0,%1,%2,%3}, [%4];"
                 : "=r"(r0), "=r"(r1), "=r"(r2), "=r"(r3) : "r"(addr));
}
static __device__ __forceinline__ void mma16816(float* d, const uint32_t* a, uint32_t b0, uint32_t b1) {
    asm volatile("mma.sync.aligned.m16n8k16.row.col.f32.bf16.bf16.f32 "
                 "{%0,%1,%2,%3}, {%4,%5,%6,%7}, {%8,%9}, {%0,%1,%2,%3};"
                 : "+f"(d[0]), "+f"(d[1]), "+f"(d[2]), "+f"(d[3])
                 : "r"(a[0]), "r"(a[1]), "r"(a[2]), "r"(a[3]), "r"(b0), "r"(b1));
}
static __device__ __forceinline__ void mma_tf32(float* d, const uint32_t* a, uint32_t b0, uint32_t b1) {
    asm volatile("mma.sync.aligned.m16n8k8.row.col.f32.tf32.tf32.f32 "
                 "{%0,%1,%2,%3}, {%4,%5,%6,%7}, {%8,%9}, {%0,%1,%2,%3};"
                 : "+f"(d[0]), "+f"(d[1]), "+f"(d[2]), "+f"(d[3])
                 : "r"(a[0]), "r"(a[1]), "r"(a[2]), "r"(a[3]), "r"(b0), "r"(b1));
}
static __device__ __forceinline__ float ex2(float x) {
    float y; asm("ex2.approx.ftz.f32 %0, %1;" : "=f"(y) : "f"(x)); return y;
}
static __device__ __forceinline__ void sts32(uint32_t addr, uint32_t v) {
    asm volatile("st.shared.b32 [%0], %1;" :: "r"(addr), "r"(v));
}
static __device__ __forceinline__ void cp16(uint32_t dst, const void* src) {
    asm volatile("cp.async.cg.shared.global [%0], [%1], 16;" :: "r"(dst), "l"(src));
}
#define CP_COMMIT asm volatile("cp.async.commit_group;" ::: "memory")
#define CP_WAIT1  asm volatile("cp.async.wait_group 1;" ::: "memory")

#define QSCALE 0.36067376022224085f   // 0.25 * log2(e)
#define CLIP2  72.134752f             // 50 * log2(e)

// ================= fused projection: V (+Q,K) via tf32 MMA, 3-stage ring =================
#define PJ_WS 0                         // 3 x 18432
#define PJ_XS 55296                     // 3 x 17408
#define PJ_BYTES (55296 + 52224)

__global__ __launch_bounds__(256, 2) void proj_kernel(
    const float* __restrict__ x,
    const float* __restrict__ Wq, const float* __restrict__ bq,
    const float* __restrict__ Wk, const float* __restrict__ bk,
    const float* __restrict__ Wv, const float* __restrict__ bv)
{
    extern __shared__ __align__(16) char sm[];
    uint32_t smU = smem_u32(sm);
    int t = threadIdx.x, wid = t >> 5, lane = t & 31;
    int mg = wid >> 1, ng = wid & 1;
    int n0 = blockIdx.x * 128, ytile = blockIdx.y, b = blockIdx.z;
    bool active = (ytile < 2) || (mg == 0);

    int wm = t >> 1, wq4 = t & 1;
    const float* wsrc;
    bool wvalid = true;
    if (ytile < 2) wsrc = Wv + (ytile * 128 + wm) * Cc;
    else {
        if (wm < 16) wsrc = Wq + wm * Cc;
        else if (wm < 32) wsrc = Wk + (wm - 16) * Cc;
        else { wsrc = Wq; wvalid = false; }
    }
    const float* xb = x + (size_t)b * Cc * Nn + n0;
    int xk = t >> 3, xn = t & 7;

    // prologue: chunks 0,1 into stages 0,1
#pragma unroll
    for (int ch = 0; ch < 2; ch++) {
        int k0 = ch * 32;
        if (wvalid) {
#pragma unroll
            for (int u = 0; u < 4; u++) {
                int kq = wq4 + 2 * u;
                cp16(smU + PJ_WS + ch * 18432 + wm * 144 + kq * 16, wsrc + k0 + kq * 4);
            }
        }
#pragma unroll
        for (int u = 0; u < 4; u++) {
            int nq = xn + 8 * u;
            cp16(smU + PJ_XS + ch * 17408 + xk * 544 + nq * 16, xb + (size_t)(k0 + xk) * Nn + nq * 4);
        }
        CP_COMMIT;
    }

    float acc[2][8][4];
#pragma unroll
    for (int i = 0; i < 2; i++)
#pragma unroll
        for (int j = 0; j < 8; j++)
#pragma unroll
            for (int q = 0; q < 4; q++) acc[i][j][q] = 0.f;

    int st = 0, sp = 2;
    for (int ch = 0; ch < 8; ch++) {
        CP_WAIT1;
        __syncthreads();
        if (ch + 2 < 8) {
            int k0 = (ch + 2) * 32;
            if (wvalid) {
#pragma unroll
                for (int u = 0; u < 4; u++) {
                    int kq = wq4 + 2 * u;
                    cp16(smU + PJ_WS + sp * 18432 + wm * 144 + kq * 16, wsrc + k0 + kq * 4);
                }
            }
#pragma unroll
            for (int u = 0; u < 4; u++) {
                int nq = xn + 8 * u;
                cp16(smU + PJ_XS + sp * 17408 + xk * 544 + nq * 16, xb + (size_t)(k0 + xk) * Nn + nq * 4);
            }
        }
        CP_COMMIT;
        if (active) {
            const float* wb = (const float*)(sm + PJ_WS + st * 18432);
            const float* xs = (const float*)(sm + PJ_XS + st * 17408);
#pragma unroll
            for (int k8 = 0; k8 < 4; k8++) {
                uint32_t A[2][4];
#pragma unroll
                for (int mi = 0; mi < 2; mi++) {
                    const float* ap = wb + (mg * 32 + mi * 16 + (lane >> 2)) * 36 + k8 * 8 + (lane & 3);
                    A[mi][0] = __float_as_uint(ap[0]);
                    A[mi][2] = __float_as_uint(ap[4]);
                    A[mi][1] = __float_as_uint(ap[8 * 36]);
                    A[mi][3] = __float_as_uint(ap[8 * 36 + 4]);
                }
                const float* bp = xs + (k8 * 8 + (lane & 3)) * 136 + ng * 64 + (lane >> 2);
#pragma unroll
                for (int nb = 0; nb < 8; nb++) {
                    uint32_t b0 = __float_as_uint(bp[nb * 8]);
                    uint32_t b1 = __float_as_uint(bp[nb * 8 + 4 * 136]);
                    mma_tf32(acc[0][nb], A[0], b0, b1);
                    mma_tf32(acc[1][nb], A[1], b0, b1);
                }
            }
        }
        st = (st == 2) ? 0 : st + 1;
        sp = (sp == 2) ? 0 : sp + 1;
    }
    __syncthreads();

    if (ytile < 2) {
        __nv_bfloat16* Tb = (__nv_bfloat16*)(sm + PJ_XS);
#pragma unroll
        for (int mi = 0; mi < 2; mi++) {
            int m = mg * 32 + mi * 16 + (lane >> 2);
            float bv0 = bv[ytile * 128 + m];
            float bv1 = bv[ytile * 128 + m + 8];
#pragma unroll
            for (int nb = 0; nb < 8; nb++) {
                int n = ng * 64 + nb * 8 + (lane & 3) * 2;
                float* a = acc[mi][nb];
                Tb[(size_t)n * 136 + m]           = __float2bfloat16(a[0] + bv0);
                Tb[(size_t)(n + 1) * 136 + m]     = __float2bfloat16(a[1] + bv0);
                Tb[(size_t)n * 136 + m + 8]       = __float2bfloat16(a[2] + bv1);
                Tb[(size_t)(n + 1) * 136 + m + 8] = __float2bfloat16(a[3] + bv1);
            }
        }
        __syncthreads();
        int n = t >> 1, c = t & 1;
        const uint4* src = (const uint4*)((const char*)Tb + n * 272 + c * 128);
        uint4* dst = (uint4*)((char*)(g_VT + ((size_t)(b * Nn + n0 + n)) * Cc + ytile * 128) + c * 128);
#pragma unroll
        for (int u = 0; u < 8; u++) dst[u] = src[u];
    } else {
        __nv_bfloat16* Qt = (__nv_bfloat16*)(sm + PJ_XS);            // [128][24]
        __nv_bfloat16* Kt = (__nv_bfloat16*)(sm + PJ_XS + 6144);     // [16][136]
        if (mg == 0) {
            {
                int d = lane >> 2;
                float b0 = bq[d], b1 = bq[d + 8];
#pragma unroll
                for (int nb = 0; nb < 8; nb++) {
                    int n = ng * 64 + nb * 8 + (lane & 3) * 2;
                    float* a = acc[0][nb];
                    Qt[(size_t)n * 24 + d]           = __float2bfloat16((a[0] + b0) * QSCALE);
                    Qt[(size_t)(n + 1) * 24 + d]     = __float2bfloat16((a[1] + b0) * QSCALE);
                    Qt[(size_t)n * 24 + d + 8]       = __float2bfloat16((a[2] + b1) * QSCALE);
                    Qt[(size_t)(n + 1) * 24 + d + 8] = __float2bfloat16((a[3] + b1) * QSCALE);
                }
            }
            {
                int d = lane >> 2;
                float b0 = bk[d], b1 = bk[d + 8];
#pragma unroll
                for (int nb = 0; nb < 8; nb++) {
                    int n = ng * 64 + nb * 8 + (lane & 3) * 2;
                    float* a = acc[1][nb];
                    Kt[(size_t)d * 136 + n]           = __float2bfloat16(a[0] + b0);
                    Kt[(size_t)d * 136 + n + 1]       = __float2bfloat16(a[1] + b0);
                    Kt[(size_t)(d + 8) * 136 + n]     = __float2bfloat16(a[2] + b1);
                    Kt[(size_t)(d + 8) * 136 + n + 1] = __float2bfloat16(a[3] + b1);
                }
            }
        }
        __syncthreads();
        {
            int n = t >> 1, c = t & 1;
            const uint4* src = (const uint4*)((const char*)Qt + n * 48 + c * 16);
            uint4* dst = (uint4*)((char*)(g_Qb + ((size_t)(b * Nn + n0 + n)) * Dd) + c * 16);
            dst[0] = src[0];
        }
        {
            int d = t >> 4, c = t & 15;
            const uint4* src = (const uint4*)((const char*)Kt + d * 272 + c * 16);
            uint4* dst = (uint4*)((char*)(g_Kb + ((size_t)(b * Dd + d)) * Nn + n0) + c * 16);
            dst[0] = src[0];
        }
    }
}

// ================= fused attention: pipelined split-role FA2, 1 sync/iter =================
// smem: VS 4x33792 | KS 4x2304 @135168 | QS 6144 @144384 | PS 2x18432 @150528 | RS 1024 @187392
#define AT_VS 0
#define AT_KS 135168
#define AT_QS 144384
#define AT_PS 150528
#define AT_RS 187392
#define AT_BYTES 188416

__global__ __launch_bounds__(512, 1) void attn_kernel()
{
    extern __shared__ __align__(16) char sm[];
    uint32_t smU = smem_u32(sm);
    int t = threadIdx.x, b = blockIdx.y, m0 = blockIdx.x * BM;
    int wid = t >> 5, lane = t & 31;
    int mg = wid >> 1, jg = wid & 1;    // QK role: m16 x j32 (disjoint)
    int mg2 = wid >> 2, eg = wid & 3;   // PV role: m32 x e64

    const char* vb = (const char*)(g_VT + (size_t)b * Nn * Cc);
    const char* kb = (const char*)(g_Kb + (size_t)b * Dd * Nn);
    const char* qb = (const char*)(g_Qb + ((size_t)b * Nn + m0) * Dd);

    int vj = t >> 3, vc = t & 7;
    int kd = t >> 3, kc = t & 7;

    // prologue: stages 0,1 (+Q)
#pragma unroll
    for (int st = 0; st < 2; st++) {
        int n0 = st * BN;
        uint32_t dst = smU + AT_VS + st * 33792 + vj * 528 + vc * 16;
        const char* src = vb + ((size_t)(n0 + vj)) * 512 + vc * 16;
#pragma unroll
        for (int u = 0; u < 4; u++) cp16(dst + u * 128, src + u * 128);
        if (t < 128) cp16(smU + AT_KS + st * 2304 + kd * 144 + kc * 16,
                          kb + (size_t)kd * (Nn * 2) + n0 * 2 + kc * 16);
        if (st == 0 && t < 256) {
            int m = t >> 1, c = t & 1;
            cp16(smU + AT_QS + m * 48 + c * 16, qb + m * 32 + c * 16);
        }
        CP_COMMIT;
    }

    float acc[2][8][4];
#pragma unroll
    for (int i = 0; i < 2; i++)
#pragma unroll
        for (int j = 0; j < 8; j++)
#pragma unroll
            for (int q = 0; q < 4; q++) acc[i][j][q] = 0.f;

    uint32_t qa[4];
    float rs0 = 0.f, rs1 = 0.f;

    uint32_t ps_st0 = smU + AT_PS + (mg * 16 + (lane >> 2)) * 144 + (jg * 32 + (lane & 3) * 2) * 2;
    uint32_t ps_ld0 = smU + AT_PS +
        (uint32_t)(mg2 * 32 + (lane & 7) + ((lane >> 3) & 1) * 8) * 144 + (lane >> 4) * 16;

    // ---- peeled: wait stage0, QK(0) -> Pbuf0 ----
    CP_WAIT1;
    __syncthreads();
    {
        uint32_t qaddr = smU + AT_QS +
            (mg * 16 + (lane & 7) + ((lane >> 3) & 1) * 8) * 48 + (lane >> 4) * 16;
        ldsm_x4(qa[0], qa[1], qa[2], qa[3], qaddr);
    }
    {
        uint32_t ksb = smU + AT_KS;      // stage 0
        uint32_t pst = ps_st0;            // buf 0
#pragma unroll
        for (int nb2 = 0; nb2 < 2; nb2++) {
            float c[2][4];
#pragma unroll
            for (int h = 0; h < 2; h++)
#pragma unroll
                for (int j = 0; j < 4; j++) c[h][j] = 0.f;
            uint32_t b0, b1, b2, b3;
            uint32_t ka = ksb + (lane & 15) * 144 + (jg * 32 + nb2 * 16 + (lane >> 4) * 8) * 2;
            ldsm_x4t(b0, b1, b2, b3, ka);
            mma16816(c[0], qa, b0, b1);
            mma16816(c[1], qa, b2, b3);
#pragma unroll
            for (int h = 0; h < 2; h++) {
                float e0 = ex2(fminf(fmaxf(c[h][0], -CLIP2), CLIP2));
                float e1 = ex2(fminf(fmaxf(c[h][1], -CLIP2), CLIP2));
                float e2 = ex2(fminf(fmaxf(c[h][2], -CLIP2), CLIP2));
                float e3 = ex2(fminf(fmaxf(c[h][3], -CLIP2), CLIP2));
                rs0 += e0 + e1;
                rs1 += e2 + e3;
                __nv_bfloat162 lo = __floats2bfloat162_rn(e0, e1);
                __nv_bfloat162 hi = __floats2bfloat162_rn(e2, e3);
                sts32(pst + nb2 * 32 + h * 16, *(uint32_t*)&lo);
                sts32(pst + nb2 * 32 + h * 16 + 8 * 144, *(uint32_t*)&hi);
            }
        }
    }

    // ---- main loop: one sync per iteration ----
    for (int it = 0; it < NTILES; it++) {
        // prefetch V/K(it+2) into stage (it+2)&3 (last read in iter it-2; safe)
        if (it + 2 < NTILES) {
            int n0 = (it + 2) * BN;
            int sp = (it + 2) & 3;
            uint32_t dst = smU + AT_VS + sp * 33792 + vj * 528 + vc * 16;
            const char* src = vb + ((size_t)(n0 + vj)) * 512 + vc * 16;
#pragma unroll
            for (int u = 0; u < 4; u++) cp16(dst + u * 128, src + u * 128);
            if (t < 128) cp16(smU + AT_KS + sp * 2304 + kd * 144 + kc * 16,
                              kb + (size_t)kd * (Nn * 2) + n0 * 2 + kc * 16);
        }
        CP_COMMIT;
        CP_WAIT1;          // V(it), K(it+1) resident
        __syncthreads();   // P(it) visible; prior-stage readers done

        // ---- QK(it+1) -> Pbuf[(it+1)&1] ----
        if (it + 1 < NTILES) {
            uint32_t ksb = smU + AT_KS + ((it + 1) & 3) * 2304;
            uint32_t pst = ps_st0 + ((it + 1) & 1) * 18432;
#pragma unroll
            for (int nb2 = 0; nb2 < 2; nb2++) {
                float c[2][4];
#pragma unroll
                for (int h = 0; h < 2; h++)
#pragma unroll
                    for (int j = 0; j < 4; j++) c[h][j] = 0.f;
                uint32_t b0, b1, b2, b3;
                uint32_t ka = ksb + (lane & 15) * 144 + (jg * 32 + nb2 * 16 + (lane >> 4) * 8) * 2;
                ldsm_x4t(b0, b1, b2, b3, ka);
                mma16816(c[0], qa, b0, b1);
                mma16816(c[1], qa, b2, b3);
#pragma unroll
                for (int h = 0; h < 2; h++) {
                    float e0 = ex2(fminf(fmaxf(c[h][0], -CLIP2), CLIP2));
                    float e1 = ex2(fminf(fmaxf(c[h][1], -CLIP2), CLIP2));
                    float e2 = ex2(fminf(fmaxf(c[h][2], -CLIP2), CLIP2));
                    float e3 = ex2(fminf(fmaxf(c[h][3], -CLIP2), CLIP2));
                    rs0 += e0 + e1;
                    rs1 += e2 + e3;
                    __nv_bfloat162 lo = __floats2bfloat162_rn(e0, e1);
                    __nv_bfloat162 hi = __floats2bfloat162_rn(e2, e3);
                    sts32(pst + nb2 * 32 + h * 16, *(uint32_t*)&lo);
                    sts32(pst + nb2 * 32 + h * 16 + 8 * 144, *(uint32_t*)&hi);
                }
            }
        }

        // ---- PV(it): Pbuf[it&1], V stage it&3 ----
        {
            uint32_t vsb = smU + AT_VS + (it & 3) * 33792;
            uint32_t pld = ps_ld0 + (it & 1) * 18432;
#pragma unroll
            for (int kg = 0; kg < 4; kg++) {
                uint32_t pA[2][4];
#pragma unroll
                for (int mi = 0; mi < 2; mi++)
                    ldsm_x4(pA[mi][0], pA[mi][1], pA[mi][2], pA[mi][3],
                            pld + mi * (16 * 144) + kg * 32);
#pragma unroll
                for (int eb2 = 0; eb2 < 4; eb2++) {
                    uint32_t b0, b1, b2, b3;
                    uint32_t va = vsb + (kg * 16 + (lane & 15)) * 528 +
                                  (eg * 64 + eb2 * 16 + (lane >> 4) * 8) * 2;
                    ldsm_x4t(b0, b1, b2, b3, va);
                    mma16816(acc[0][eb2 * 2],     pA[0], b0, b1);
                    mma16816(acc[0][eb2 * 2 + 1], pA[0], b2, b3);
                    mma16816(acc[1][eb2 * 2],     pA[1], b0, b1);
                    mma16816(acc[1][eb2 * 2 + 1], pA[1], b2, b3);
                }
            }
        }
    }

    // rowsum reduce + stash
    rs0 += __shfl_xor_sync(0xffffffffu, rs0, 1);
    rs0 += __shfl_xor_sync(0xffffffffu, rs0, 2);
    rs1 += __shfl_xor_sync(0xffffffffu, rs1, 1);
    rs1 += __shfl_xor_sync(0xffffffffu, rs1, 2);
    float* rs_s = (float*)(sm + AT_RS);
    if ((lane & 3) == 0) {
        rs_s[jg * 128 + mg * 16 + (lane >> 2)]     = rs0;
        rs_s[jg * 128 + mg * 16 + (lane >> 2) + 8] = rs1;
    }

    // epilogue: normalize -> smem stage [e128 x 132] -> coalesced stores (2 e-halves)
    float* Tf = (float*)sm;
    float* ob = g_OA + (size_t)b * Cc * Nn + m0;
    int r = lane >> 2, q = lane & 3;
#pragma unroll
    for (int h = 0; h < 2; h++) {
        __syncthreads();
        if ((eg >> 1) == h) {
            int ebase = (eg & 1) * 64;
#pragma unroll
            for (int mi = 0; mi < 2; mi++) {
                int ml = mg2 * 32 + mi * 16 + r;
                float inv0 = 1.f / (rs_s[ml]     + rs_s[128 + ml]);
                float inv1 = 1.f / (rs_s[ml + 8] + rs_s[128 + ml + 8]);
#pragma unroll
                for (int nb = 0; nb < 8; nb++) {
                    int e = ebase + nb * 8 + 2 * q;
                    float* a = acc[mi][nb];
                    Tf[(size_t)e * 132 + ml]           = a[0] * inv0;
                    Tf[(size_t)(e + 1) * 132 + ml]     = a[1] * inv0;
                    Tf[(size_t)e * 132 + ml + 8]       = a[2] * inv1;
                    Tf[(size_t)(e + 1) * 132 + ml + 8] = a[3] * inv1;
                }
            }
        }
        __syncthreads();
#pragma unroll
        for (int rr = 0; rr < 8; rr++) {
            int e = wid * 8 + rr;
            const float* srcr = Tf + (size_t)e * 132;
            float* dstr = ob + (size_t)(h * 128 + e) * Nn;
#pragma unroll
            for (int c = 0; c < 4; c++)
                dstr[c * 32 + lane] = srcr[c * 32 + lane];
        }
    }
}

// ================= output projection via tf32 MMA, 3-stage ring + residual =================
__global__ __launch_bounds__(256, 2) void outproj_kernel(
    const float* __restrict__ x,
    const float* __restrict__ Wo, const float* __restrict__ bo,
    const float* __restrict__ gamma, float* __restrict__ out)
{
    extern __shared__ __align__(16) char sm[];
    uint32_t smU = smem_u32(sm);
    int t = threadIdx.x, wid = t >> 5, lane = t & 31;
    int mg = wid >> 1, ng = wid & 1;
    int n0 = blockIdx.x * 128, ytile = blockIdx.y, b = blockIdx.z;

    int wm = t >> 1, wq4 = t & 1;
    const float* wsrc = Wo + (ytile * 128 + wm) * Cc;
    const float* xb = g_OA + (size_t)b * Cc * Nn + n0;
    int xk = t >> 3, xn = t & 7;

#pragma unroll
    for (int ch = 0; ch < 2; ch++) {
        int k0 = ch * 32;
#pragma unroll
        for (int u = 0; u < 4; u++) {
            int kq = wq4 + 2 * u;
            cp16(smU + PJ_WS + ch * 18432 + wm * 144 + kq * 16, wsrc + k0 + kq * 4);
        }
#pragma unroll
        for (int u = 0; u < 4; u++) {
            int nq = xn + 8 * u;
            cp16(smU + PJ_XS + ch * 17408 + xk * 544 + nq * 16, xb + (size_t)(k0 + xk) * Nn + nq * 4);
        }
        CP_COMMIT;
    }

    float acc[2][8][4];
#pragma unroll
    for (int i = 0; i < 2; i++)
#pragma unroll
        for (int j = 0; j < 8; j++)
#pragma unroll
            for (int q = 0; q < 4; q++) acc[i][j][q] = 0.f;

    int st = 0, sp = 2;
    for (int ch = 0; ch < 8; ch++) {
        CP_WAIT1;
        __syncthreads();
        if (ch + 2 < 8) {
            int k0 = (ch + 2) * 32;
#pragma unroll
            for (int u = 0; u < 4; u++) {
                int kq = wq4 + 2 * u;
                cp16(smU + PJ_WS + sp * 18432 + wm * 144 + kq * 16, wsrc + k0 + kq * 4);
            }
#pragma unroll
            for (int u = 0; u < 4; u++) {
                int nq = xn + 8 * u;
                cp16(smU + PJ_XS + sp * 17408 + xk * 544 + nq * 16, xb + (size_t)(k0 + xk) * Nn + nq * 4);
            }
        }
        CP_COMMIT;
        {
            const float* wb = (const float*)(sm + PJ_WS + st * 18432);
            const float* xs = (const float*)(sm + PJ_XS + st * 17408);
#pragma unroll
            for (int k8 = 0; k8 < 4; k8++) {
                uint32_t A[2][4];
#pragma unroll
                for (int mi = 0; mi < 2; mi++) {
                    const float* ap = wb + (mg * 32 + mi * 16 + (lane >> 2)) * 36 + k8 * 8 + (lane & 3);
                    A[mi][0] = __float_as_uint(ap[0]);
                    A[mi][2] = __float_as_uint(ap[4]);
                    A[mi][1] = __float_as_uint(ap[8 * 36]);
                    A[mi][3] = __float_as_uint(ap[8 * 36 + 4]);
                }
                const float* bp = xs + (k8 * 8 + (lane & 3)) * 136 + ng * 64 + (lane >> 2);
#pragma unroll
                for (int nb = 0; nb < 8; nb++) {
                    uint32_t b0 = __float_as_uint(bp[nb * 8]);
                    uint32_t b1 = __float_as_uint(bp[nb * 8 + 4 * 136]);
                    mma_tf32(acc[0][nb], A[0], b0, b1);
                    mma_tf32(acc[1][nb], A[1], b0, b1);
                }
            }
        }
        st = (st == 2) ? 0 : st + 1;
        sp = (sp == 2) ? 0 : sp + 1;
    }
    __syncthreads();

    float* Tf = (float*)sm;
#pragma unroll
    for (int mi = 0; mi < 2; mi++) {
        int m = mg * 32 + mi * 16 + (lane >> 2);
#pragma unroll
        for (int nb = 0; nb < 8; nb++) {
            int n = ng * 64 + nb * 8 + (lane & 3) * 2;
            float* a = acc[mi][nb];
            *(float2*)(Tf + (size_t)m * 132 + n)       = make_float2(a[0], a[1]);
            *(float2*)(Tf + (size_t)(m + 8) * 132 + n) = make_float2(a[2], a[3]);
        }
    }
    __syncthreads();
    float g = fminf(fmaxf(gamma[0], 0.f), 1.f);
    {
        int m = t >> 1, c = t & 1;
        int mglob = ytile * 128 + m;
        float bb = bo[mglob];
        size_t base = ((size_t)(b * Cc + mglob)) * Nn + n0 + c * 64;
#pragma unroll
        for (int u = 0; u < 16; u++) {
            float4 v = *(const float4*)(Tf + (size_t)m * 132 + c * 64 + u * 4);
            float4 xr = *(const float4*)(x + base + u * 4);
            float4 o;
            o.x = g * (v.x + bb) + xr.x;
            o.y = g * (v.y + bb) + xr.y;
            o.z = g * (v.z + bb) + xr.z;
            o.w = g * (v.w + bb) + xr.w;
            *(float4*)(out + base + u * 4) = o;
        }
    }
}

// ---------------- launcher ----------------
extern "C" void kernel_launch(void* const* d_in, const int* in_sizes, int n_in,
                              void* d_out, int out_size)
{
    const float* x     = (const float*)d_in[0];
    const float* Wq    = (const float*)d_in[1];
    const float* bq    = (const float*)d_in[2];
    const float* Wk    = (const float*)d_in[3];
    const float* bk    = (const float*)d_in[4];
    const float* Wv    = (const float*)d_in[5];
    const float* bv    = (const float*)d_in[6];
    const float* Wo    = (const float*)d_in[7];
    const float* bo    = (const float*)d_in[8];
    const float* gamma = (const float*)d_in[9];
    float* out = (float*)d_out;

    cudaFuncSetAttribute(proj_kernel,    cudaFuncAttributeMaxDynamicSharedMemorySize, PJ_BYTES);
    cudaFuncSetAttribute(outproj_kernel, cudaFuncAttributeMaxDynamicSharedMemorySize, PJ_BYTES);
    cudaFuncSetAttribute(attn_kernel,    cudaFuncAttributeMaxDynamicSharedMemorySize, AT_BYTES);

    proj_kernel   <<<dim3(Nn / 128, 3, Bb), 256, PJ_BYTES>>>(x, Wq, bq, Wk, bk, Wv, bv);
    attn_kernel   <<<dim3(Nn / BM, Bb), 512, AT_BYTES>>>();
    outproj_kernel<<<dim3(Nn / 128, 2, Bb), 256, PJ_BYTES>>>(x, Wo, bo, gamma, out);
}